// round 3
// baseline (speedup 1.0000x reference)
#include <cuda_runtime.h>
#include <cuda_bf16.h>
#include <cstddef>

#define Bn 2
#define Cc 64
#define Hh 256
#define Ww 256
#define HW (Hh*Ww)

typedef unsigned long long ull;

// -------- scratch (static device globals; no runtime alloc allowed) --------
__device__ float g_A[(size_t)Bn*Cc*HW];           // 33.5 MB
__device__ float g_B[(size_t)Bn*Cc*HW];           // 33.5 MB

// ---------------- packed f32x2 helpers ----------------
__device__ __forceinline__ ull pack2(float lo, float hi) {
    ull r; asm("mov.b64 %0, {%1, %2};" : "=l"(r) : "f"(lo), "f"(hi)); return r;
}
__device__ __forceinline__ void unpack2(ull v, float& lo, float& hi) {
    asm("mov.b64 {%0, %1}, %2;" : "=f"(lo), "=f"(hi) : "l"(v));
}
__device__ __forceinline__ ull ffma2(ull a, ull b, ull c) {
    ull d; asm("fma.rn.f32x2 %0, %1, %2, %3;" : "=l"(d) : "l"(a), "l"(b), "l"(c)); return d;
}
__device__ __forceinline__ ull add2(ull a, ull b) {
    ull d; asm("add.rn.f32x2 %0, %1, %2;" : "=l"(d) : "l"(a), "l"(b)); return d;
}

// ---------------------------------------------------------------------------
// 1x1 fuse conv: concat(image, guidance) [128ch] -> 64ch, + bias, PReLU(a)
// grid (64 tiles, 4 cog, B), block 256. Thread: 4 px, 8 packed j-pairs (16 ch).
// ---------------------------------------------------------------------------
__global__ void __launch_bounds__(256, 2)
fuse1x1_k(const float* __restrict__ img,
          const float* __restrict__ gui,
          const float* __restrict__ w,     // [64][128]
          const float* __restrict__ bias,  // [64]
          const float* __restrict__ a_ptr,
          float* __restrict__ out)
{
    __shared__ ull s_wp[8*128];   // packed (co pair) weights for this cog
    const int tid = threadIdx.x;
    const int tile = blockIdx.x;
    const int cog = blockIdx.y;
    const int b = blockIdx.z;

    for (int e = tid; e < 8*128; e += 256) {
        int jp = e >> 7, ci = e & 127;
        int co0 = cog*16 + 2*jp;
        s_wp[e] = pack2(w[co0*128 + ci], w[(co0+1)*128 + ci]);
    }
    __syncthreads();

    const int p0 = tile*1024 + tid;
    ull acc[8][4];
#pragma unroll
    for (int jp = 0; jp < 8; ++jp) {
        int co0 = cog*16 + 2*jp;
        ull bv = pack2(bias[co0], bias[co0+1]);
#pragma unroll
        for (int q = 0; q < 4; ++q) acc[jp][q] = bv;
    }

    const float* i0 = img + (size_t)b*Cc*HW + p0;
    const float* i1 = gui + (size_t)b*Cc*HW + p0;
#pragma unroll 2
    for (int ci = 0; ci < 64; ++ci) {
        const float* ic = i0 + (size_t)ci*HW;
        ull vp[4];
#pragma unroll
        for (int q = 0; q < 4; ++q) { float v = ic[q*256]; vp[q] = pack2(v, v); }
#pragma unroll
        for (int jp = 0; jp < 8; ++jp) {
            ull wv = s_wp[jp*128 + ci];
#pragma unroll
            for (int q = 0; q < 4; ++q) acc[jp][q] = ffma2(vp[q], wv, acc[jp][q]);
        }
    }
#pragma unroll 2
    for (int ci = 0; ci < 64; ++ci) {
        const float* ic = i1 + (size_t)ci*HW;
        ull vp[4];
#pragma unroll
        for (int q = 0; q < 4; ++q) { float v = ic[q*256]; vp[q] = pack2(v, v); }
#pragma unroll
        for (int jp = 0; jp < 8; ++jp) {
            ull wv = s_wp[jp*128 + 64 + ci];
#pragma unroll
            for (int q = 0; q < 4; ++q) acc[jp][q] = ffma2(vp[q], wv, acc[jp][q]);
        }
    }

    const float a = a_ptr[0];
#pragma unroll
    for (int jp = 0; jp < 8; ++jp) {
        int co0 = cog*16 + 2*jp;
        float* o0 = out + ((size_t)b*Cc + co0)*HW + p0;
        float* o1 = o0 + HW;
#pragma unroll
        for (int q = 0; q < 4; ++q) {
            float lo, hi; unpack2(acc[jp][q], lo, hi);
            lo = (lo >= 0.f) ? lo : a*lo;
            hi = (hi >= 0.f) ? hi : a*hi;
            o0[q*256] = lo;
            o1[q*256] = hi;
        }
    }
}

// ---------------------------------------------------------------------------
// 3x3 conv, 64->64, pad 1, optional PReLU, optional residual.
// grid (W/32, H/8, B); block 256. Tile 32x8 spatial, ALL 64 out-ch in block.
// Thread: 8 px (one row segment) x 4 co-pairs (8 out-ch).
//   tid: jpg = tid>>5 (out-ch group of 8), lane: row = (lane>>2), xq = lane&3.
// Weights staged [k][co-pair] so 4 pairs load as 2x LDS.128 per tap.
// Input halo 10x34 staged with row stride 35 (conflict-free tap reads).
// Per input channel per thread: 288 FFMA2 vs 18 LDS.128 + 30 LDS.32.
// ---------------------------------------------------------------------------
template<bool PRELU, bool RESID>
__global__ void __launch_bounds__(256, 1)
conv3x3_k(const float* __restrict__ in,
          const float* __restrict__ w,     // [64][64][3][3]
          const float* __restrict__ bias,
          const float* __restrict__ a_ptr,
          const float* __restrict__ resid,
          float* __restrict__ out)
{
    __shared__ float s_in[2][10*35];
    __shared__ ull   s_wp[2][9*32];      // [ci-sub][k*32 + co_pair]

    const int tid = threadIdx.x;
    const int x0  = blockIdx.x * 32;
    const int y0  = blockIdx.y * 8;
    const int b   = blockIdx.z;
    const int jpg = tid >> 5;          // 0..7 -> out-ch base jpg*8
    const int lane = tid & 31;
    const int row = lane >> 2;         // 0..7
    const int xs  = (lane & 3) * 8;    // 0,8,16,24

    ull acc[4][8];
#pragma unroll
    for (int j = 0; j < 4; ++j) {
        int co0 = jpg*8 + 2*j;
        ull bv = pack2(bias[co0], bias[co0+1]);
#pragma unroll
        for (int px = 0; px < 8; ++px) acc[j][px] = bv;
    }

    const float* inb = in + (size_t)b*Cc*HW;

    for (int cb = 0; cb < Cc; cb += 2) {
        // stage two input-channel halo tiles (10 rows x 34 cols, stride 35)
#pragma unroll
        for (int e0 = 0; e0 < 768; e0 += 256) {
            int e = e0 + tid;
            if (e < 680) {
                int cc  = e >= 340;
                int idx = e - cc*340;
                int r   = idx / 34;
                int c2  = idx - r*34;
                int gy = y0 - 1 + r;
                int gx = x0 - 1 + c2;
                float v = 0.f;
                if ((unsigned)gy < (unsigned)Hh && (unsigned)gx < (unsigned)Ww)
                    v = inb[(size_t)(cb + cc)*HW + gy*Ww + gx];
                s_in[cc][r*35 + c2] = v;
            }
        }
        // stage packed weights: [cc][k*32 + pair]
#pragma unroll
        for (int e0 = 0; e0 < 768; e0 += 256) {
            int e = e0 + tid;
            if (e < 576) {
                int cc  = e >= 288;
                int rem = e - cc*288;
                int k   = rem >> 5;
                int pr  = rem & 31;
                int co0 = 2*pr;
                int ci  = cb + cc;
                s_wp[cc][k*32 + pr] =
                    pack2(w[(co0*Cc + ci)*9 + k], w[((co0+1)*Cc + ci)*9 + k]);
            }
        }
        __syncthreads();

#pragma unroll
        for (int cc = 0; cc < 2; ++cc) {
            // taps: 3 rows x 10 cols, packed {t,t}
            ull tp[3][10];
#pragma unroll
            for (int dy = 0; dy < 3; ++dy)
#pragma unroll
                for (int c = 0; c < 10; ++c) {
                    float t = s_in[cc][(row + dy)*35 + xs + c];
                    tp[dy][c] = pack2(t, t);
                }
#pragma unroll
            for (int k = 0; k < 9; ++k) {
                const int dy = k / 3, dx = k - (k/3)*3;
                const ulonglong2* wp =
                    (const ulonglong2*)&s_wp[cc][k*32 + jpg*4];
                ulonglong2 w01 = wp[0];
                ulonglong2 w23 = wp[1];
#pragma unroll
                for (int px = 0; px < 8; ++px) {
                    ull a = tp[dy][px + dx];
                    acc[0][px] = ffma2(a, w01.x, acc[0][px]);
                    acc[1][px] = ffma2(a, w01.y, acc[1][px]);
                    acc[2][px] = ffma2(a, w23.x, acc[2][px]);
                    acc[3][px] = ffma2(a, w23.y, acc[3][px]);
                }
            }
        }
        __syncthreads();
    }

    float a = 0.f;
    if (PRELU) a = a_ptr[0];
    const int y = y0 + row;
    const int x = x0 + xs;
#pragma unroll
    for (int j = 0; j < 4; ++j) {
        int co0 = jpg*8 + 2*j;
        float v0[8], v1[8];
#pragma unroll
        for (int px = 0; px < 8; ++px) {
            unpack2(acc[j][px], v0[px], v1[px]);
            if (PRELU) {
                v0[px] = (v0[px] >= 0.f) ? v0[px] : a*v0[px];
                v1[px] = (v1[px] >= 0.f) ? v1[px] : a*v1[px];
            }
        }
        size_t o0 = ((size_t)(b*Cc + co0)*Hh + y)*Ww + x;
        size_t o1 = o0 + (size_t)HW;
        float4* d0 = (float4*)(out + o0);
        float4* d1 = (float4*)(out + o1);
        float4 a0 = make_float4(v0[0], v0[1], v0[2], v0[3]);
        float4 a1 = make_float4(v0[4], v0[5], v0[6], v0[7]);
        float4 b0 = make_float4(v1[0], v1[1], v1[2], v1[3]);
        float4 b1 = make_float4(v1[4], v1[5], v1[6], v1[7]);
        if (RESID) {
            const float4* r0 = (const float4*)(resid + o0);
            const float4* r1 = (const float4*)(resid + o1);
            float4 x0v = r0[0], x1v = r0[1], y0v = r1[0], y1v = r1[1];
            a0.x += x0v.x; a0.y += x0v.y; a0.z += x0v.z; a0.w += x0v.w;
            a1.x += x1v.x; a1.y += x1v.y; a1.z += x1v.z; a1.w += x1v.w;
            b0.x += y0v.x; b0.y += y0v.y; b0.z += y0v.z; b0.w += y0v.w;
            b1.x += y1v.x; b1.y += y1v.y; b1.z += y1v.z; b1.w += y1v.w;
        }
        d0[0] = a0; d0[1] = a1;
        d1[0] = b0; d1[1] = b1;
    }
}

// ---------------------------------------------------------------------------
// FUSED: kg5 1x1 (64->576) + bias + dynamic joint-bilateral filter.
// Weight rows read as LDS.128 (2 packed pairs each) -> FMA-bound.
// grid (HW/256, B); block 256; 1 px/thread; w5 fully staged in 147KB smem.
// ---------------------------------------------------------------------------
__global__ void __launch_bounds__(256, 1)
kgjbf_k(const float* __restrict__ y4,    // [B][64][HW]
        const float* __restrict__ w5,    // [576][64]
        const float* __restrict__ b5,    // [576]
        const float* __restrict__ img,   // [B][64][HW]
        float* __restrict__ out)         // [B][64][HW]
{
    extern __shared__ float smem[];
    float* s_w5 = smem;            // 36864 floats
    float* s_b5 = smem + 36864;    // 576 floats

    const int tid = threadIdx.x;
    const int b = blockIdx.y;
    const int p = blockIdx.x * 256 + tid;
    const int y = p >> 8;
    const int x = p & 255;

    {
        const float4* src = (const float4*)w5;
        float4* dst = (float4*)s_w5;
        for (int e = tid; e < 9216; e += 256) dst[e] = src[e];
        for (int e = tid; e < 576; e += 256) s_b5[e] = b5[e];
    }
    __syncthreads();

    // load y4 pixel, packed over ci pairs
    ull yp[32];
    {
        const float* yb = y4 + (size_t)b*Cc*HW + p;
#pragma unroll
        for (int c2 = 0; c2 < 32; ++c2)
            yp[c2] = pack2(yb[(size_t)(2*c2)*HW], yb[(size_t)(2*c2+1)*HW]);
    }

    const float* ib = img + (size_t)b*Cc*HW;
    float* ob = out + (size_t)b*Cc*HW + p;

    for (int ci = 0; ci < 64; ++ci) {
        float acc = 0.f;
#pragma unroll
        for (int kk = 0; kk < 9; ++kk) {
            const int f = kk*64 + ci;
            const ulonglong2* wrow = (const ulonglong2*)(s_w5 + f*64);
            ull p0 = 0ULL, p1 = 0ULL, p2 = 0ULL, p3 = 0ULL;
#pragma unroll
            for (int c4 = 0; c4 < 16; c4 += 4) {
                ulonglong2 wv0 = wrow[c4  ];
                ulonglong2 wv1 = wrow[c4+1];
                ulonglong2 wv2 = wrow[c4+2];
                ulonglong2 wv3 = wrow[c4+3];
                p0 = ffma2(yp[2*c4  ], wv0.x, p0);
                p1 = ffma2(yp[2*c4+1], wv0.y, p1);
                p2 = ffma2(yp[2*c4+2], wv1.x, p2);
                p3 = ffma2(yp[2*c4+3], wv1.y, p3);
                p0 = ffma2(yp[2*c4+4], wv2.x, p0);
                p1 = ffma2(yp[2*c4+5], wv2.y, p1);
                p2 = ffma2(yp[2*c4+6], wv3.x, p2);
                p3 = ffma2(yp[2*c4+7], wv3.y, p3);
            }
            p0 = add2(p0, p1); p2 = add2(p2, p3); p0 = add2(p0, p2);
            float lo, hi; unpack2(p0, lo, hi);
            float bik = lo + hi + s_b5[f];

            int ch  = f / 9;
            int tap = f - ch*9;
            int dy  = tap / 3 - 1;
            int dx  = tap - (tap/3)*3 - 1;
            int yy = y + dy, xx = x + dx;
            float iv = 0.f;
            if ((unsigned)yy < (unsigned)Hh && (unsigned)xx < (unsigned)Ww)
                iv = ib[(size_t)ch*HW + yy*Ww + xx];
            acc = fmaf(bik, iv, acc);
        }
        ob[(size_t)ci*HW] = acc;
    }
}

// ---------------------------------------------------------------------------
extern "C" void kernel_launch(void* const* d_in, const int* in_sizes, int n_in,
                              void* d_out, int out_size)
{
    const float* image   = (const float*)d_in[0];
    const float* guidance= (const float*)d_in[1];
    const float* tensor_w= (const float*)d_in[2];
    const float* tensor_b= (const float*)d_in[3];
    const float* a_jbf   = (const float*)d_in[4];
    const float* kg_w1   = (const float*)d_in[5];
    const float* kg_b1   = (const float*)d_in[6];
    const float* kg_w2   = (const float*)d_in[7];
    const float* kg_b2   = (const float*)d_in[8];
    const float* kg_w3   = (const float*)d_in[9];
    const float* kg_b3   = (const float*)d_in[10];
    const float* kg_w4   = (const float*)d_in[11];
    const float* kg_b4   = (const float*)d_in[12];
    const float* kg_w5   = (const float*)d_in[13];
    const float* kg_b5   = (const float*)d_in[14];
    const float* a_kg    = (const float*)d_in[15];
    const float* jbf_w1  = (const float*)d_in[16];
    const float* jbf_b1  = (const float*)d_in[17];
    const float* jbf_w2  = (const float*)d_in[18];
    const float* jbf_b2  = (const float*)d_in[19];
    float* out = (float*)d_out;

    float *A, *Bb;
    cudaGetSymbolAddress((void**)&A,  g_A);
    cudaGetSymbolAddress((void**)&Bb, g_B);

    static bool attr_set = false;
    if (!attr_set) {
        cudaFuncSetAttribute(kgjbf_k, cudaFuncAttributeMaxDynamicSharedMemorySize, 149760);
        attr_set = true;
    }

    dim3 blk(256);
    dim3 gf(64, 4, Bn);
    dim3 g3(Ww/32, Hh/8, Bn);
    dim3 gj(HW/256, Bn);

    // t = PReLU(conv1x1(cat(image, guidance)))           -> A
    fuse1x1_k<<<gf, blk>>>(image, guidance, tensor_w, tensor_b, a_jbf, A);
    // kg tower
    conv3x3_k<true,false><<<g3, blk>>>(A,  kg_w1, kg_b1, a_kg, nullptr, Bb);
    conv3x3_k<true,false><<<g3, blk>>>(Bb, kg_w2, kg_b2, a_kg, nullptr, A);
    conv3x3_k<true,false><<<g3, blk>>>(A,  kg_w3, kg_b3, a_kg, nullptr, Bb);
    conv3x3_k<true,false><<<g3, blk>>>(Bb, kg_w4, kg_b4, a_kg, nullptr, A);
    // fused kg5 + dynamic filter                          -> Bb (= jbf)
    kgjbf_k<<<gj, blk, 149760>>>(A, kg_w5, kg_b5, image, Bb);
    // jbf_conv: 3x3 + PReLU(a_jbf), 3x3, + image residual -> d_out
    conv3x3_k<true,false><<<g3, blk>>>(Bb, jbf_w1, jbf_b1, a_jbf, nullptr, A);
    conv3x3_k<false,true><<<g3, blk>>>(A,  jbf_w2, jbf_b2, nullptr, image, out);
}

// round 4
// speedup vs baseline: 1.4785x; 1.4785x over previous
#include <cuda_runtime.h>
#include <cuda_bf16.h>
#include <cstddef>

#define Bn 2
#define Cc 64
#define Hh 256
#define Ww 256
#define HW (Hh*Ww)

typedef unsigned long long ull;

// -------- scratch (static device globals; no runtime alloc allowed) --------
__device__ float g_A[(size_t)Bn*Cc*HW];           // 33.5 MB
__device__ float g_B[(size_t)Bn*Cc*HW];           // 33.5 MB

// ---------------- packed f32x2 helpers ----------------
__device__ __forceinline__ ull pack2(float lo, float hi) {
    ull r; asm("mov.b64 %0, {%1, %2};" : "=l"(r) : "f"(lo), "f"(hi)); return r;
}
__device__ __forceinline__ void unpack2(ull v, float& lo, float& hi) {
    asm("mov.b64 {%0, %1}, %2;" : "=f"(lo), "=f"(hi) : "l"(v));
}
__device__ __forceinline__ ull ffma2(ull a, ull b, ull c) {
    ull d; asm("fma.rn.f32x2 %0, %1, %2, %3;" : "=l"(d) : "l"(a), "l"(b), "l"(c)); return d;
}
__device__ __forceinline__ ull add2(ull a, ull b) {
    ull d; asm("add.rn.f32x2 %0, %1, %2;" : "=l"(d) : "l"(a), "l"(b)); return d;
}

// ---------------------------------------------------------------------------
// 1x1 fuse conv: concat(image, guidance) [128ch] -> 64ch, + bias, PReLU(a)
// ---------------------------------------------------------------------------
__global__ void __launch_bounds__(256, 2)
fuse1x1_k(const float* __restrict__ img,
          const float* __restrict__ gui,
          const float* __restrict__ w,     // [64][128]
          const float* __restrict__ bias,  // [64]
          const float* __restrict__ a_ptr,
          float* __restrict__ out)
{
    __shared__ ull s_wp[8*128];
    const int tid = threadIdx.x;
    const int tile = blockIdx.x;
    const int cog = blockIdx.y;
    const int b = blockIdx.z;

    for (int e = tid; e < 8*128; e += 256) {
        int jp = e >> 7, ci = e & 127;
        int co0 = cog*16 + 2*jp;
        s_wp[e] = pack2(w[co0*128 + ci], w[(co0+1)*128 + ci]);
    }
    __syncthreads();

    const int p0 = tile*1024 + tid;
    ull acc[8][4];
#pragma unroll
    for (int jp = 0; jp < 8; ++jp) {
        int co0 = cog*16 + 2*jp;
        ull bv = pack2(bias[co0], bias[co0+1]);
#pragma unroll
        for (int q = 0; q < 4; ++q) acc[jp][q] = bv;
    }

    const float* i0 = img + (size_t)b*Cc*HW + p0;
    const float* i1 = gui + (size_t)b*Cc*HW + p0;
#pragma unroll 2
    for (int ci = 0; ci < 64; ++ci) {
        const float* ic = i0 + (size_t)ci*HW;
        ull vp[4];
#pragma unroll
        for (int q = 0; q < 4; ++q) { float v = ic[q*256]; vp[q] = pack2(v, v); }
#pragma unroll
        for (int jp = 0; jp < 8; ++jp) {
            ull wv = s_wp[jp*128 + ci];
#pragma unroll
            for (int q = 0; q < 4; ++q) acc[jp][q] = ffma2(vp[q], wv, acc[jp][q]);
        }
    }
#pragma unroll 2
    for (int ci = 0; ci < 64; ++ci) {
        const float* ic = i1 + (size_t)ci*HW;
        ull vp[4];
#pragma unroll
        for (int q = 0; q < 4; ++q) { float v = ic[q*256]; vp[q] = pack2(v, v); }
#pragma unroll
        for (int jp = 0; jp < 8; ++jp) {
            ull wv = s_wp[jp*128 + 64 + ci];
#pragma unroll
            for (int q = 0; q < 4; ++q) acc[jp][q] = ffma2(vp[q], wv, acc[jp][q]);
        }
    }

    const float a = a_ptr[0];
#pragma unroll
    for (int jp = 0; jp < 8; ++jp) {
        int co0 = cog*16 + 2*jp;
        float* o0 = out + ((size_t)b*Cc + co0)*HW + p0;
        float* o1 = o0 + HW;
#pragma unroll
        for (int q = 0; q < 4; ++q) {
            float lo, hi; unpack2(acc[jp][q], lo, hi);
            lo = (lo >= 0.f) ? lo : a*lo;
            hi = (hi >= 0.f) ? hi : a*hi;
            o0[q*256] = lo;
            o1[q*256] = hi;
        }
    }
}

// ---------------------------------------------------------------------------
// 3x3 conv, 64->64, pad 1, optional PReLU, optional residual.
// grid (8, 32, B*2); block 256. Tile 32x8 spatial, 32 out-ch per block (cog).
// Thread: 8 px (row segment) x 2 co-pairs (4 out-ch).
//   jpg = tid>>5 (8 groups of 4 ch); lane: row=(lane>>2), xs=(lane&3)*8.
// Register-prefetch double buffering hides staging LDG latency.
// 2 CTAs/SM (launch_bounds 256,2). Per ci per thread: 144 FFMA2 vs
// 15 LDS.32 (conflict-free) + 9 LDS.128 (broadcast).
// ---------------------------------------------------------------------------
template<bool PRELU, bool RESID>
__global__ void __launch_bounds__(256, 2)
conv3x3_k(const float* __restrict__ in,
          const float* __restrict__ w,     // [64][64][3][3]
          const float* __restrict__ bias,
          const float* __restrict__ a_ptr,
          const float* __restrict__ resid,
          float* __restrict__ out)
{
    __shared__ float s_in[2][10*35];
    __shared__ __align__(16) ull s_wp[288];   // [cc][k][16 pairs]

    const int tid = threadIdx.x;
    const int x0  = blockIdx.x * 32;
    const int y0  = blockIdx.y * 8;
    const int cog = blockIdx.z & 1;
    const int b   = blockIdx.z >> 1;
    const int jpg = tid >> 5;            // 0..7 -> 4 ch each
    const int lane = tid & 31;
    const int row = lane >> 2;           // 0..7
    const int xs  = (lane & 3) * 8;      // 0,8,16,24

    const int co0 = cog*32 + jpg*4;      // this thread's first out-channel

    ull acc[2][8];
#pragma unroll
    for (int j = 0; j < 2; ++j) {
        ull bv = pack2(bias[co0 + 2*j], bias[co0 + 2*j + 1]);
#pragma unroll
        for (int px = 0; px < 8; ++px) acc[j][px] = bv;
    }

    const float* inb = in + (size_t)b*Cc*HW;

    // prefetch registers
    float h[3];
    float wl[2], wh[2];

    // ---- prefetch halo + weights for channel pair cb ----
    auto issue_prefetch = [&](int cb) {
#pragma unroll
        for (int q = 0; q < 3; ++q) {
            int e = tid + q*256;
            if (e < 680) {
                int cc  = e >= 340;
                int idx = e - cc*340;
                int r   = idx / 34;
                int c2  = idx - r*34;
                int gy = y0 - 1 + r;
                int gx = x0 - 1 + c2;
                float v = 0.f;
                if ((unsigned)gy < (unsigned)Hh && (unsigned)gx < (unsigned)Ww)
                    v = __ldg(&inb[(size_t)(cb + cc)*HW + gy*Ww + gx]);
                h[q] = v;
            }
        }
#pragma unroll
        for (int q = 0; q < 2; ++q) {
            int e = tid + q*256;
            if (e < 288) {
                int cc  = e / 144;
                int rem = e - cc*144;
                int k   = rem >> 4;
                int pr  = rem & 15;
                int c0  = cog*32 + pr*2;
                int ci  = cb + cc;
                wl[q] = __ldg(&w[(c0*Cc + ci)*9 + k]);
                wh[q] = __ldg(&w[((c0+1)*Cc + ci)*9 + k]);
            }
        }
    };

    issue_prefetch(0);

    for (int cb = 0; cb < Cc; cb += 2) {
        __syncthreads();   // previous compute finished (no-op on first iter)
        // store staged registers into smem
#pragma unroll
        for (int q = 0; q < 3; ++q) {
            int e = tid + q*256;
            if (e < 680) {
                int cc  = e >= 340;
                int idx = e - cc*340;
                int r   = idx / 34;
                int c2  = idx - r*34;
                s_in[cc][r*35 + c2] = h[q];
            }
        }
#pragma unroll
        for (int q = 0; q < 2; ++q) {
            int e = tid + q*256;
            if (e < 288) s_wp[e] = pack2(wl[q], wh[q]);
        }
        __syncthreads();

        // prefetch next channel pair (overlaps with compute below)
        if (cb + 2 < Cc) issue_prefetch(cb + 2);

        // compute on the two staged channels
#pragma unroll
        for (int cc = 0; cc < 2; ++cc) {
#pragma unroll
            for (int dy = 0; dy < 3; ++dy) {
                ull tp[10];
#pragma unroll
                for (int c = 0; c < 10; ++c) {
                    float t = s_in[cc][(row + dy)*35 + xs + c];
                    tp[c] = pack2(t, t);
                }
#pragma unroll
                for (int dx = 0; dx < 3; ++dx) {
                    int k = dy*3 + dx;
                    ulonglong2 w2 = *(const ulonglong2*)&s_wp[cc*144 + k*16 + jpg*2];
#pragma unroll
                    for (int px = 0; px < 8; ++px) {
                        ull a = tp[px + dx];
                        acc[0][px] = ffma2(a, w2.x, acc[0][px]);
                        acc[1][px] = ffma2(a, w2.y, acc[1][px]);
                    }
                }
            }
        }
    }

    float a = 0.f;
    if (PRELU) a = a_ptr[0];
    const int y = y0 + row;
    const int x = x0 + xs;
#pragma unroll
    for (int j = 0; j < 2; ++j) {
        float v0[8], v1[8];
#pragma unroll
        for (int px = 0; px < 8; ++px) {
            unpack2(acc[j][px], v0[px], v1[px]);
            if (PRELU) {
                v0[px] = (v0[px] >= 0.f) ? v0[px] : a*v0[px];
                v1[px] = (v1[px] >= 0.f) ? v1[px] : a*v1[px];
            }
        }
        size_t o0 = ((size_t)(b*Cc + co0 + 2*j)*Hh + y)*Ww + x;
        size_t o1 = o0 + (size_t)HW;
        float4 a0 = make_float4(v0[0], v0[1], v0[2], v0[3]);
        float4 a1 = make_float4(v0[4], v0[5], v0[6], v0[7]);
        float4 b0 = make_float4(v1[0], v1[1], v1[2], v1[3]);
        float4 b1 = make_float4(v1[4], v1[5], v1[6], v1[7]);
        if (RESID) {
            const float4* r0 = (const float4*)(resid + o0);
            const float4* r1 = (const float4*)(resid + o1);
            float4 x0v = r0[0], x1v = r0[1], y0v = r1[0], y1v = r1[1];
            a0.x += x0v.x; a0.y += x0v.y; a0.z += x0v.z; a0.w += x0v.w;
            a1.x += x1v.x; a1.y += x1v.y; a1.z += x1v.z; a1.w += x1v.w;
            b0.x += y0v.x; b0.y += y0v.y; b0.z += y0v.z; b0.w += y0v.w;
            b1.x += y1v.x; b1.y += y1v.y; b1.z += y1v.z; b1.w += y1v.w;
        }
        float4* d0 = (float4*)(out + o0);
        float4* d1 = (float4*)(out + o1);
        d0[0] = a0; d0[1] = a1;
        d1[0] = b0; d1[1] = b1;
    }
}

// ---------------------------------------------------------------------------
// FUSED: kg5 1x1 (64->576) + bias + dynamic joint-bilateral filter.
// ---------------------------------------------------------------------------
__global__ void __launch_bounds__(256, 1)
kgjbf_k(const float* __restrict__ y4,    // [B][64][HW]
        const float* __restrict__ w5,    // [576][64]
        const float* __restrict__ b5,    // [576]
        const float* __restrict__ img,   // [B][64][HW]
        float* __restrict__ out)         // [B][64][HW]
{
    extern __shared__ float smem[];
    float* s_w5 = smem;            // 36864 floats
    float* s_b5 = smem + 36864;    // 576 floats

    const int tid = threadIdx.x;
    const int b = blockIdx.y;
    const int p = blockIdx.x * 256 + tid;
    const int y = p >> 8;
    const int x = p & 255;

    {
        const float4* src = (const float4*)w5;
        float4* dst = (float4*)s_w5;
        for (int e = tid; e < 9216; e += 256) dst[e] = src[e];
        for (int e = tid; e < 576; e += 256) s_b5[e] = b5[e];
    }
    __syncthreads();

    ull yp[32];
    {
        const float* yb = y4 + (size_t)b*Cc*HW + p;
#pragma unroll
        for (int c2 = 0; c2 < 32; ++c2)
            yp[c2] = pack2(yb[(size_t)(2*c2)*HW], yb[(size_t)(2*c2+1)*HW]);
    }

    const float* ib = img + (size_t)b*Cc*HW;
    float* ob = out + (size_t)b*Cc*HW + p;

    for (int ci = 0; ci < 64; ++ci) {
        float acc = 0.f;
#pragma unroll
        for (int kk = 0; kk < 9; ++kk) {
            const int f = kk*64 + ci;
            const ulonglong2* wrow = (const ulonglong2*)(s_w5 + f*64);
            ull p0 = 0ULL, p1 = 0ULL, p2 = 0ULL, p3 = 0ULL;
#pragma unroll
            for (int c4 = 0; c4 < 16; c4 += 4) {
                ulonglong2 wv0 = wrow[c4  ];
                ulonglong2 wv1 = wrow[c4+1];
                ulonglong2 wv2 = wrow[c4+2];
                ulonglong2 wv3 = wrow[c4+3];
                p0 = ffma2(yp[2*c4  ], wv0.x, p0);
                p1 = ffma2(yp[2*c4+1], wv0.y, p1);
                p2 = ffma2(yp[2*c4+2], wv1.x, p2);
                p3 = ffma2(yp[2*c4+3], wv1.y, p3);
                p0 = ffma2(yp[2*c4+4], wv2.x, p0);
                p1 = ffma2(yp[2*c4+5], wv2.y, p1);
                p2 = ffma2(yp[2*c4+6], wv3.x, p2);
                p3 = ffma2(yp[2*c4+7], wv3.y, p3);
            }
            p0 = add2(p0, p1); p2 = add2(p2, p3); p0 = add2(p0, p2);
            float lo, hi; unpack2(p0, lo, hi);
            float bik = lo + hi + s_b5[f];

            int ch  = f / 9;
            int tap = f - ch*9;
            int dy  = tap / 3 - 1;
            int dx  = tap - (tap/3)*3 - 1;
            int yy = y + dy, xx = x + dx;
            float iv = 0.f;
            if ((unsigned)yy < (unsigned)Hh && (unsigned)xx < (unsigned)Ww)
                iv = ib[(size_t)ch*HW + yy*Ww + xx];
            acc = fmaf(bik, iv, acc);
        }
        ob[(size_t)ci*HW] = acc;
    }
}

// ---------------------------------------------------------------------------
extern "C" void kernel_launch(void* const* d_in, const int* in_sizes, int n_in,
                              void* d_out, int out_size)
{
    const float* image   = (const float*)d_in[0];
    const float* guidance= (const float*)d_in[1];
    const float* tensor_w= (const float*)d_in[2];
    const float* tensor_b= (const float*)d_in[3];
    const float* a_jbf   = (const float*)d_in[4];
    const float* kg_w1   = (const float*)d_in[5];
    const float* kg_b1   = (const float*)d_in[6];
    const float* kg_w2   = (const float*)d_in[7];
    const float* kg_b2   = (const float*)d_in[8];
    const float* kg_w3   = (const float*)d_in[9];
    const float* kg_b3   = (const float*)d_in[10];
    const float* kg_w4   = (const float*)d_in[11];
    const float* kg_b4   = (const float*)d_in[12];
    const float* kg_w5   = (const float*)d_in[13];
    const float* kg_b5   = (const float*)d_in[14];
    const float* a_kg    = (const float*)d_in[15];
    const float* jbf_w1  = (const float*)d_in[16];
    const float* jbf_b1  = (const float*)d_in[17];
    const float* jbf_w2  = (const float*)d_in[18];
    const float* jbf_b2  = (const float*)d_in[19];
    float* out = (float*)d_out;

    float *A, *Bb;
    cudaGetSymbolAddress((void**)&A,  g_A);
    cudaGetSymbolAddress((void**)&Bb, g_B);

    static bool attr_set = false;
    if (!attr_set) {
        cudaFuncSetAttribute(kgjbf_k, cudaFuncAttributeMaxDynamicSharedMemorySize, 149760);
        attr_set = true;
    }

    dim3 blk(256);
    dim3 gf(64, 4, Bn);
    dim3 g3(Ww/32, Hh/8, Bn*2);
    dim3 gj(HW/256, Bn);

    fuse1x1_k<<<gf, blk>>>(image, guidance, tensor_w, tensor_b, a_jbf, A);
    conv3x3_k<true,false><<<g3, blk>>>(A,  kg_w1, kg_b1, a_kg, nullptr, Bb);
    conv3x3_k<true,false><<<g3, blk>>>(Bb, kg_w2, kg_b2, a_kg, nullptr, A);
    conv3x3_k<true,false><<<g3, blk>>>(A,  kg_w3, kg_b3, a_kg, nullptr, Bb);
    conv3x3_k<true,false><<<g3, blk>>>(Bb, kg_w4, kg_b4, a_kg, nullptr, A);
    kgjbf_k<<<gj, blk, 149760>>>(A, kg_w5, kg_b5, image, Bb);
    conv3x3_k<true,false><<<g3, blk>>>(Bb, jbf_w1, jbf_b1, a_jbf, nullptr, A);
    conv3x3_k<false,true><<<g3, blk>>>(A,  jbf_w2, jbf_b2, nullptr, image, out);
}

// round 5
// speedup vs baseline: 1.5817x; 1.0698x over previous
#include <cuda_runtime.h>
#include <cuda_bf16.h>
#include <cstddef>

#define Bn 2
#define Cc 64
#define Hh 256
#define Ww 256
#define HW (Hh*Ww)

typedef unsigned long long ull;

// -------- scratch (static device globals; no runtime alloc allowed) --------
__device__ float g_A[(size_t)Bn*Cc*HW];           // 33.5 MB
__device__ float g_B[(size_t)Bn*Cc*HW];           // 33.5 MB
__device__ ull   g_WP[6*2*64*9*16];               // packed conv weights, 884KB

// ---------------- packed f32x2 helpers ----------------
__device__ __forceinline__ ull pack2(float lo, float hi) {
    ull r; asm("mov.b64 %0, {%1, %2};" : "=l"(r) : "f"(lo), "f"(hi)); return r;
}
__device__ __forceinline__ void unpack2(ull v, float& lo, float& hi) {
    asm("mov.b64 {%0, %1}, %2;" : "=f"(lo), "=f"(hi) : "l"(v));
}
__device__ __forceinline__ ull ffma2(ull a, ull b, ull c) {
    ull d; asm("fma.rn.f32x2 %0, %1, %2, %3;" : "=l"(d) : "l"(a), "l"(b), "l"(c)); return d;
}
__device__ __forceinline__ ull add2(ull a, ull b) {
    ull d; asm("add.rn.f32x2 %0, %1, %2;" : "=l"(d) : "l"(a), "l"(b)); return d;
}
__device__ __forceinline__ unsigned smem_u32(const void* p) {
    unsigned a;
    asm("{ .reg .u64 t; cvta.to.shared.u64 t, %1; cvt.u32.u64 %0, t; }"
        : "=r"(a) : "l"(p));
    return a;
}
__device__ __forceinline__ void cp_async4(unsigned dst, const void* src, int src_sz) {
    asm volatile("cp.async.ca.shared.global [%0], [%1], 4, %2;"
                 :: "r"(dst), "l"(src), "r"(src_sz) : "memory");
}
__device__ __forceinline__ void cp_async16(unsigned dst, const void* src) {
    asm volatile("cp.async.cg.shared.global [%0], [%1], 16;"
                 :: "r"(dst), "l"(src) : "memory");
}
__device__ __forceinline__ void cp_commit() {
    asm volatile("cp.async.commit_group;" ::: "memory");
}
template<int N>
__device__ __forceinline__ void cp_wait() {
    asm volatile("cp.async.wait_group %0;" :: "n"(N) : "memory");
}

// ---------------------------------------------------------------------------
// one-shot weight packer: wp[layer][cog][ci][k][pr] = pack2(w[co0][ci][k],
// w[co0+1][ci][k]), co0 = cog*32 + pr*2.   110592 elements.
// ---------------------------------------------------------------------------
__global__ void pack_w_k(const float* __restrict__ w0, const float* __restrict__ w1,
                         const float* __restrict__ w2, const float* __restrict__ w3,
                         const float* __restrict__ w4, const float* __restrict__ w5,
                         ull* __restrict__ wp)
{
    int idx = blockIdx.x*256 + threadIdx.x;
    if (idx >= 110592) return;
    int layer = idx / 18432; int r = idx - layer*18432;
    int cog = r / 9216;      r -= cog*9216;
    int ci  = r / 144;       r -= ci*144;
    int k   = r / 16;        int pr = r - k*16;
    const float* w = (layer==0)?w0:(layer==1)?w1:(layer==2)?w2:
                     (layer==3)?w3:(layer==4)?w4:w5;
    int co0 = cog*32 + pr*2;
    wp[idx] = pack2(w[(co0*Cc + ci)*9 + k], w[((co0+1)*Cc + ci)*9 + k]);
}

// ---------------------------------------------------------------------------
// 1x1 fuse conv: concat(image, guidance) [128ch] -> 64ch, + bias, PReLU(a)
// ---------------------------------------------------------------------------
__global__ void __launch_bounds__(256, 2)
fuse1x1_k(const float* __restrict__ img,
          const float* __restrict__ gui,
          const float* __restrict__ w,     // [64][128]
          const float* __restrict__ bias,  // [64]
          const float* __restrict__ a_ptr,
          float* __restrict__ out)
{
    __shared__ ull s_wp[8*128];
    const int tid = threadIdx.x;
    const int tile = blockIdx.x;
    const int cog = blockIdx.y;
    const int b = blockIdx.z;

    for (int e = tid; e < 8*128; e += 256) {
        int jp = e >> 7, ci = e & 127;
        int co0 = cog*16 + 2*jp;
        s_wp[e] = pack2(w[co0*128 + ci], w[(co0+1)*128 + ci]);
    }
    __syncthreads();

    const int p0 = tile*1024 + tid;
    ull acc[8][4];
#pragma unroll
    for (int jp = 0; jp < 8; ++jp) {
        int co0 = cog*16 + 2*jp;
        ull bv = pack2(bias[co0], bias[co0+1]);
#pragma unroll
        for (int q = 0; q < 4; ++q) acc[jp][q] = bv;
    }

    const float* i0 = img + (size_t)b*Cc*HW + p0;
    const float* i1 = gui + (size_t)b*Cc*HW + p0;
#pragma unroll 2
    for (int ci = 0; ci < 64; ++ci) {
        const float* ic = i0 + (size_t)ci*HW;
        ull vp[4];
#pragma unroll
        for (int q = 0; q < 4; ++q) { float v = ic[q*256]; vp[q] = pack2(v, v); }
#pragma unroll
        for (int jp = 0; jp < 8; ++jp) {
            ull wv = s_wp[jp*128 + ci];
#pragma unroll
            for (int q = 0; q < 4; ++q) acc[jp][q] = ffma2(vp[q], wv, acc[jp][q]);
        }
    }
#pragma unroll 2
    for (int ci = 0; ci < 64; ++ci) {
        const float* ic = i1 + (size_t)ci*HW;
        ull vp[4];
#pragma unroll
        for (int q = 0; q < 4; ++q) { float v = ic[q*256]; vp[q] = pack2(v, v); }
#pragma unroll
        for (int jp = 0; jp < 8; ++jp) {
            ull wv = s_wp[jp*128 + 64 + ci];
#pragma unroll
            for (int q = 0; q < 4; ++q) acc[jp][q] = ffma2(vp[q], wv, acc[jp][q]);
        }
    }

    const float a = a_ptr[0];
#pragma unroll
    for (int jp = 0; jp < 8; ++jp) {
        int co0 = cog*16 + 2*jp;
        float* o0 = out + ((size_t)b*Cc + co0)*HW + p0;
        float* o1 = o0 + HW;
#pragma unroll
        for (int q = 0; q < 4; ++q) {
            float lo, hi; unpack2(acc[jp][q], lo, hi);
            lo = (lo >= 0.f) ? lo : a*lo;
            hi = (hi >= 0.f) ? hi : a*hi;
            o0[q*256] = lo;
            o1[q*256] = hi;
        }
    }
}

// ---------------------------------------------------------------------------
// 3x3 conv, 64->64, pad 1, optional PReLU, optional residual.
// grid (8, 32, B*2); block 256. Tile 32x8, 32 out-ch per block (cog).
// cp.async 3-stage ring, 4 input channels per stage, 1 barrier per stage.
// Thread: 8 px x 2 co-pairs. Per stage: 576 FFMA2 vs ~7 LDGSTS + 120 LDS
//  + 36 LDS.128(broadcast). 2 CTAs/SM.
// ---------------------------------------------------------------------------
template<bool PRELU, bool RESID>
__global__ void __launch_bounds__(256, 2)
conv3x3_k(const float* __restrict__ in,
          const ull*   __restrict__ wp,    // packed [cog][ci][k][16]
          const float* __restrict__ bias,
          const float* __restrict__ a_ptr,
          const float* __restrict__ resid,
          float* __restrict__ out)
{
    __shared__ float s_in[3][4][352];
    __shared__ __align__(16) ull s_w[3][4][144];

    const int tid = threadIdx.x;
    const int x0  = blockIdx.x * 32;
    const int y0  = blockIdx.y * 8;
    const int cog = blockIdx.z & 1;
    const int b   = blockIdx.z >> 1;
    const int jpg = tid >> 5;            // 0..7 -> 4 ch each
    const int lane = tid & 31;
    const int row = lane >> 2;           // 0..7
    const int xs  = (lane & 3) * 8;      // 0,8,16,24
    const int co0 = cog*32 + jpg*4;

    ull acc[2][8];
#pragma unroll
    for (int j = 0; j < 2; ++j) {
        ull bv = pack2(bias[co0 + 2*j], bias[co0 + 2*j + 1]);
#pragma unroll
        for (int px = 0; px < 8; ++px) acc[j][px] = bv;
    }

    const float* inb = in + (size_t)b*Cc*HW;
    const ull* wpg = wp + (size_t)cog*(64*144);

    auto issue = [&](int st, int cb) {
        // halo: 4 channels x 340 elements = 1360 4B transfers
#pragma unroll
        for (int q = 0; q < 6; ++q) {
            int e = tid + q*256;
            if (e < 1360) {
                int cc  = e / 340;
                int idx = e - cc*340;
                int r   = idx / 34;
                int c2  = idx - r*34;
                int gy = y0 - 1 + r;
                int gx = x0 - 1 + c2;
                bool ok = ((unsigned)gy < (unsigned)Hh) & ((unsigned)gx < (unsigned)Ww);
                const float* src = ok ? (inb + (size_t)(cb + cc)*HW + gy*Ww + gx) : inb;
                unsigned dst = smem_u32(&s_in[st][cc][r*35 + c2]);
                cp_async4(dst, src, ok ? 4 : 0);
            }
        }
        // weights: 4 channels x 1152B = 288 x 16B transfers
#pragma unroll
        for (int q = 0; q < 2; ++q) {
            int e = tid + q*256;
            if (e < 288) {
                int cc = e / 72, ch = e - cc*72;
                const ull* src = wpg + (size_t)(cb + cc)*144 + ch*2;
                unsigned dst = smem_u32(&s_w[st][cc][ch*2]);
                cp_async16(dst, src);
            }
        }
        cp_commit();
    };

    issue(0, 0);
    issue(1, 4);

    for (int s = 0; s < 16; ++s) {
        if (s >= 14) cp_wait<0>(); else cp_wait<1>();
        __syncthreads();
        if (s + 2 < 16) issue((s + 2) % 3, (s + 2) * 4);

        const int st = s % 3;
#pragma unroll
        for (int cc = 0; cc < 4; ++cc) {
#pragma unroll
            for (int dy = 0; dy < 3; ++dy) {
                ull tp[10];
#pragma unroll
                for (int c = 0; c < 10; ++c) {
                    float t = s_in[st][cc][(row + dy)*35 + xs + c];
                    tp[c] = pack2(t, t);
                }
#pragma unroll
                for (int dx = 0; dx < 3; ++dx) {
                    int k = dy*3 + dx;
                    ulonglong2 w2 = *(const ulonglong2*)&s_w[st][cc][k*16 + jpg*2];
#pragma unroll
                    for (int px = 0; px < 8; ++px) {
                        ull a = tp[px + dx];
                        acc[0][px] = ffma2(a, w2.x, acc[0][px]);
                        acc[1][px] = ffma2(a, w2.y, acc[1][px]);
                    }
                }
            }
        }
        __syncthreads();
    }

    float a = 0.f;
    if (PRELU) a = a_ptr[0];
    const int y = y0 + row;
    const int x = x0 + xs;
#pragma unroll
    for (int j = 0; j < 2; ++j) {
        float v0[8], v1[8];
#pragma unroll
        for (int px = 0; px < 8; ++px) {
            unpack2(acc[j][px], v0[px], v1[px]);
            if (PRELU) {
                v0[px] = (v0[px] >= 0.f) ? v0[px] : a*v0[px];
                v1[px] = (v1[px] >= 0.f) ? v1[px] : a*v1[px];
            }
        }
        size_t o0 = ((size_t)(b*Cc + co0 + 2*j)*Hh + y)*Ww + x;
        size_t o1 = o0 + (size_t)HW;
        float4 a0 = make_float4(v0[0], v0[1], v0[2], v0[3]);
        float4 a1 = make_float4(v0[4], v0[5], v0[6], v0[7]);
        float4 b0 = make_float4(v1[0], v1[1], v1[2], v1[3]);
        float4 b1 = make_float4(v1[4], v1[5], v1[6], v1[7]);
        if (RESID) {
            const float4* r0 = (const float4*)(resid + o0);
            const float4* r1 = (const float4*)(resid + o1);
            float4 x0v = r0[0], x1v = r0[1], y0v = r1[0], y1v = r1[1];
            a0.x += x0v.x; a0.y += x0v.y; a0.z += x0v.z; a0.w += x0v.w;
            a1.x += x1v.x; a1.y += x1v.y; a1.z += x1v.z; a1.w += x1v.w;
            b0.x += y0v.x; b0.y += y0v.y; b0.z += y0v.z; b0.w += y0v.w;
            b1.x += y1v.x; b1.y += y1v.y; b1.z += y1v.z; b1.w += y1v.w;
        }
        float4* d0 = (float4*)(out + o0);
        float4* d1 = (float4*)(out + o1);
        d0[0] = a0; d0[1] = a1;
        d1[0] = b0; d1[1] = b1;
    }
}

// ---------------------------------------------------------------------------
// FUSED: kg5 1x1 (64->576) + bias + dynamic joint-bilateral filter.
// 512 threads/block (16 warps), 1 px/thread, w5 staged in 147KB smem.
// ---------------------------------------------------------------------------
__global__ void __launch_bounds__(512, 1)
kgjbf_k(const float* __restrict__ y4,    // [B][64][HW]
        const float* __restrict__ w5,    // [576][64]
        const float* __restrict__ b5,    // [576]
        const float* __restrict__ img,   // [B][64][HW]
        float* __restrict__ out)         // [B][64][HW]
{
    extern __shared__ float smem[];
    float* s_w5 = smem;            // 36864 floats
    float* s_b5 = smem + 36864;    // 576 floats

    const int tid = threadIdx.x;
    const int b = blockIdx.y;
    const int p = blockIdx.x * 512 + tid;
    const int y = p >> 8;
    const int x = p & 255;

    {
        const float4* src = (const float4*)w5;
        float4* dst = (float4*)s_w5;
        for (int e = tid; e < 9216; e += 512) dst[e] = src[e];
        for (int e = tid; e < 576; e += 512) s_b5[e] = b5[e];
    }
    __syncthreads();

    ull yp[32];
    {
        const float* yb = y4 + (size_t)b*Cc*HW + p;
#pragma unroll
        for (int c2 = 0; c2 < 32; ++c2)
            yp[c2] = pack2(yb[(size_t)(2*c2)*HW], yb[(size_t)(2*c2+1)*HW]);
    }

    const float* ib = img + (size_t)b*Cc*HW;
    float* ob = out + (size_t)b*Cc*HW + p;

    for (int ci = 0; ci < 64; ++ci) {
        float acc = 0.f;
#pragma unroll
        for (int kk = 0; kk < 9; ++kk) {
            const int f = kk*64 + ci;
            const ulonglong2* wrow = (const ulonglong2*)(s_w5 + f*64);
            ull p0 = 0ULL, p1 = 0ULL, p2 = 0ULL, p3 = 0ULL;
#pragma unroll
            for (int c4 = 0; c4 < 16; c4 += 4) {
                ulonglong2 wv0 = wrow[c4  ];
                ulonglong2 wv1 = wrow[c4+1];
                ulonglong2 wv2 = wrow[c4+2];
                ulonglong2 wv3 = wrow[c4+3];
                p0 = ffma2(yp[2*c4  ], wv0.x, p0);
                p1 = ffma2(yp[2*c4+1], wv0.y, p1);
                p2 = ffma2(yp[2*c4+2], wv1.x, p2);
                p3 = ffma2(yp[2*c4+3], wv1.y, p3);
                p0 = ffma2(yp[2*c4+4], wv2.x, p0);
                p1 = ffma2(yp[2*c4+5], wv2.y, p1);
                p2 = ffma2(yp[2*c4+6], wv3.x, p2);
                p3 = ffma2(yp[2*c4+7], wv3.y, p3);
            }
            p0 = add2(p0, p1); p2 = add2(p2, p3); p0 = add2(p0, p2);
            float lo, hi; unpack2(p0, lo, hi);
            float bik = lo + hi + s_b5[f];

            int ch  = f / 9;
            int tap = f - ch*9;
            int dy  = tap / 3 - 1;
            int dx  = tap - (tap/3)*3 - 1;
            int yy = y + dy, xx = x + dx;
            float iv = 0.f;
            if ((unsigned)yy < (unsigned)Hh && (unsigned)xx < (unsigned)Ww)
                iv = ib[(size_t)ch*HW + yy*Ww + xx];
            acc = fmaf(bik, iv, acc);
        }
        ob[(size_t)ci*HW] = acc;
    }
}

// ---------------------------------------------------------------------------
extern "C" void kernel_launch(void* const* d_in, const int* in_sizes, int n_in,
                              void* d_out, int out_size)
{
    const float* image   = (const float*)d_in[0];
    const float* guidance= (const float*)d_in[1];
    const float* tensor_w= (const float*)d_in[2];
    const float* tensor_b= (const float*)d_in[3];
    const float* a_jbf   = (const float*)d_in[4];
    const float* kg_w1   = (const float*)d_in[5];
    const float* kg_b1   = (const float*)d_in[6];
    const float* kg_w2   = (const float*)d_in[7];
    const float* kg_b2   = (const float*)d_in[8];
    const float* kg_w3   = (const float*)d_in[9];
    const float* kg_b3   = (const float*)d_in[10];
    const float* kg_w4   = (const float*)d_in[11];
    const float* kg_b4   = (const float*)d_in[12];
    const float* kg_w5   = (const float*)d_in[13];
    const float* kg_b5   = (const float*)d_in[14];
    const float* a_kg    = (const float*)d_in[15];
    const float* jbf_w1  = (const float*)d_in[16];
    const float* jbf_b1  = (const float*)d_in[17];
    const float* jbf_w2  = (const float*)d_in[18];
    const float* jbf_b2  = (const float*)d_in[19];
    float* out = (float*)d_out;

    float *A, *Bb;
    ull* WP;
    cudaGetSymbolAddress((void**)&A,  g_A);
    cudaGetSymbolAddress((void**)&Bb, g_B);
    cudaGetSymbolAddress((void**)&WP, g_WP);

    static bool attr_set = false;
    if (!attr_set) {
        cudaFuncSetAttribute(kgjbf_k, cudaFuncAttributeMaxDynamicSharedMemorySize, 149760);
        attr_set = true;
    }

    dim3 blk(256);
    dim3 gf(64, 4, Bn);
    dim3 g3(Ww/32, Hh/8, Bn*2);
    dim3 gj(HW/512, Bn);

    // pack all six 3x3 conv weight tensors (layer order: kg1..kg4, jbf1, jbf2)
    pack_w_k<<<(110592 + 255)/256, blk>>>(kg_w1, kg_w2, kg_w3, kg_w4, jbf_w1, jbf_w2, WP);

    fuse1x1_k<<<gf, blk>>>(image, guidance, tensor_w, tensor_b, a_jbf, A);
    conv3x3_k<true,false><<<g3, blk>>>(A,  WP + 0*18432, kg_b1, a_kg, nullptr, Bb);
    conv3x3_k<true,false><<<g3, blk>>>(Bb, WP + 1*18432, kg_b2, a_kg, nullptr, A);
    conv3x3_k<true,false><<<g3, blk>>>(A,  WP + 2*18432, kg_b3, a_kg, nullptr, Bb);
    conv3x3_k<true,false><<<g3, blk>>>(Bb, WP + 3*18432, kg_b4, a_kg, nullptr, A);
    kgjbf_k<<<gj, dim3(512), 149760>>>(A, kg_w5, kg_b5, image, Bb);
    conv3x3_k<true,false><<<g3, blk>>>(Bb, WP + 4*18432, jbf_b1, a_jbf, nullptr, A);
    conv3x3_k<false,true><<<g3, blk>>>(A,  WP + 5*18432, jbf_b2, nullptr, image, out);
}

// round 7
// speedup vs baseline: 1.5897x; 1.0051x over previous
#include <cuda_runtime.h>
#include <cuda_bf16.h>
#include <cstddef>

#define Bn 2
#define Cc 64
#define Hh 256
#define Ww 256
#define HW (Hh*Ww)

typedef unsigned long long ull;

// -------- scratch (static device globals; no runtime alloc allowed) --------
__device__ float g_A[(size_t)Bn*Cc*HW];           // 33.5 MB
__device__ float g_B[(size_t)Bn*Cc*HW];           // 33.5 MB
__device__ ull   g_WP[6*64*9*32];                 // packed conv weights, 884KB

// ---------------- packed f32x2 helpers ----------------
__device__ __forceinline__ ull pack2(float lo, float hi) {
    ull r; asm("mov.b64 %0, {%1, %2};" : "=l"(r) : "f"(lo), "f"(hi)); return r;
}
__device__ __forceinline__ void unpack2(ull v, float& lo, float& hi) {
    asm("mov.b64 {%0, %1}, %2;" : "=f"(lo), "=f"(hi) : "l"(v));
}
__device__ __forceinline__ ull ffma2(ull a, ull b, ull c) {
    ull d; asm("fma.rn.f32x2 %0, %1, %2, %3;" : "=l"(d) : "l"(a), "l"(b), "l"(c)); return d;
}
__device__ __forceinline__ ull add2(ull a, ull b) {
    ull d; asm("add.rn.f32x2 %0, %1, %2;" : "=l"(d) : "l"(a), "l"(b)); return d;
}
__device__ __forceinline__ unsigned smem_u32(const void* p) {
    unsigned a;
    asm("{ .reg .u64 t; cvta.to.shared.u64 t, %1; cvt.u32.u64 %0, t; }"
        : "=r"(a) : "l"(p));
    return a;
}
__device__ __forceinline__ void cp_async4(unsigned dst, const void* src, int src_sz) {
    asm volatile("cp.async.ca.shared.global [%0], [%1], 4, %2;"
                 :: "r"(dst), "l"(src), "r"(src_sz) : "memory");
}
__device__ __forceinline__ void cp_async16(unsigned dst, const void* src) {
    asm volatile("cp.async.cg.shared.global [%0], [%1], 16;"
                 :: "r"(dst), "l"(src) : "memory");
}
__device__ __forceinline__ void cp_commit() {
    asm volatile("cp.async.commit_group;" ::: "memory");
}
template<int N>
__device__ __forceinline__ void cp_wait() {
    asm volatile("cp.async.wait_group %0;" :: "n"(N) : "memory");
}

// ---------------------------------------------------------------------------
// one-shot weight packer: wp[layer][ci][k][pr] = pack2(w[2pr][ci][k],
// w[2pr+1][ci][k]).  110592 elements total.
// ---------------------------------------------------------------------------
__global__ void pack_w_k(const float* __restrict__ w0, const float* __restrict__ w1,
                         const float* __restrict__ w2, const float* __restrict__ w3,
                         const float* __restrict__ w4, const float* __restrict__ w5,
                         ull* __restrict__ wp)
{
    int idx = blockIdx.x*256 + threadIdx.x;
    if (idx >= 110592) return;
    int layer = idx / 18432; int r = idx - layer*18432;
    int ci  = r / 288;       r -= ci*288;
    int k   = r / 32;        int pr = r - k*32;
    const float* w = (layer==0)?w0:(layer==1)?w1:(layer==2)?w2:
                     (layer==3)?w3:(layer==4)?w4:w5;
    int co0 = pr*2;
    wp[idx] = pack2(w[(co0*Cc + ci)*9 + k], w[((co0+1)*Cc + ci)*9 + k]);
}

// ---------------------------------------------------------------------------
// 1x1 fuse conv: concat(image, guidance) [128ch] -> 64ch, + bias, PReLU(a)
// ---------------------------------------------------------------------------
__global__ void __launch_bounds__(256, 2)
fuse1x1_k(const float* __restrict__ img,
          const float* __restrict__ gui,
          const float* __restrict__ w,     // [64][128]
          const float* __restrict__ bias,  // [64]
          const float* __restrict__ a_ptr,
          float* __restrict__ out)
{
    __shared__ ull s_wp[8*128];
    const int tid = threadIdx.x;
    const int tile = blockIdx.x;
    const int cog = blockIdx.y;
    const int b = blockIdx.z;

    for (int e = tid; e < 8*128; e += 256) {
        int jp = e >> 7, ci = e & 127;
        int co0 = cog*16 + 2*jp;
        s_wp[e] = pack2(w[co0*128 + ci], w[(co0+1)*128 + ci]);
    }
    __syncthreads();

    const int p0 = tile*1024 + tid;
    ull acc[8][4];
#pragma unroll
    for (int jp = 0; jp < 8; ++jp) {
        int co0 = cog*16 + 2*jp;
        ull bv = pack2(bias[co0], bias[co0+1]);
#pragma unroll
        for (int q = 0; q < 4; ++q) acc[jp][q] = bv;
    }

    const float* i0 = img + (size_t)b*Cc*HW + p0;
    const float* i1 = gui + (size_t)b*Cc*HW + p0;
#pragma unroll 2
    for (int ci = 0; ci < 64; ++ci) {
        const float* ic = i0 + (size_t)ci*HW;
        ull vp[4];
#pragma unroll
        for (int q = 0; q < 4; ++q) { float v = ic[q*256]; vp[q] = pack2(v, v); }
#pragma unroll
        for (int jp = 0; jp < 8; ++jp) {
            ull wv = s_wp[jp*128 + ci];
#pragma unroll
            for (int q = 0; q < 4; ++q) acc[jp][q] = ffma2(vp[q], wv, acc[jp][q]);
        }
    }
#pragma unroll 2
    for (int ci = 0; ci < 64; ++ci) {
        const float* ic = i1 + (size_t)ci*HW;
        ull vp[4];
#pragma unroll
        for (int q = 0; q < 4; ++q) { float v = ic[q*256]; vp[q] = pack2(v, v); }
#pragma unroll
        for (int jp = 0; jp < 8; ++jp) {
            ull wv = s_wp[jp*128 + 64 + ci];
#pragma unroll
            for (int q = 0; q < 4; ++q) acc[jp][q] = ffma2(vp[q], wv, acc[jp][q]);
        }
    }

    const float a = a_ptr[0];
#pragma unroll
    for (int jp = 0; jp < 8; ++jp) {
        int co0 = cog*16 + 2*jp;
        float* o0 = out + ((size_t)b*Cc + co0)*HW + p0;
        float* o1 = o0 + HW;
#pragma unroll
        for (int q = 0; q < 4; ++q) {
            float lo, hi; unpack2(acc[jp][q], lo, hi);
            lo = (lo >= 0.f) ? lo : a*lo;
            hi = (hi >= 0.f) ? hi : a*hi;
            o0[q*256] = lo;
            o1[q*256] = hi;
        }
    }
}

// ---------------------------------------------------------------------------
// 3x3 conv, 64->64, pad 1, optional PReLU, optional residual.
// grid (8, 32, B); block 256. Tile 32x8, ALL 64 out-ch per block.
// Thread: 2 adjacent rows x 4 px x 8 out-ch (4 co-pairs).
// cp.async 3-stage ring, 4 input channels/stage, ONE barrier per stage.
// ---------------------------------------------------------------------------
template<bool PRELU, bool RESID>
__global__ void __launch_bounds__(256, 2)
conv3x3_k(const float* __restrict__ in,
          const ull*   __restrict__ wp,    // packed [ci][k][32]
          const float* __restrict__ bias,
          const float* __restrict__ a_ptr,
          const float* __restrict__ resid,
          float* __restrict__ out)
{
    __shared__ float s_in[3][4][350];                 // 10 rows x 34, stride 35
    __shared__ __align__(16) ull s_w[3][4][288];      // [ci-sub][k*32 + pr]

    const int tid = threadIdx.x;
    const int x0  = blockIdx.x * 32;
    const int y0  = blockIdx.y * 8;
    const int b   = blockIdx.z;
    const int wg  = tid >> 5;            // 0..7 -> ch base wg*8
    const int lane = tid & 31;
    const int rp  = lane >> 3;           // 0..3 (row pair)
    const int xs  = (lane & 7) * 4;      // 0,4,...,28
    const int co0 = wg*8;

    ull acc[4][2][4];                    // [co-pair][row][px]
#pragma unroll
    for (int j = 0; j < 4; ++j) {
        ull bv = pack2(bias[co0 + 2*j], bias[co0 + 2*j + 1]);
#pragma unroll
        for (int L = 0; L < 2; ++L)
#pragma unroll
            for (int px = 0; px < 4; ++px) acc[j][L][px] = bv;
    }

    const float* inb = in + (size_t)b*Cc*HW;

    auto issue = [&](int st, int cb) {
        // halo: 4 channels x 340 elements
#pragma unroll
        for (int q = 0; q < 6; ++q) {
            int e = tid + q*256;
            if (e < 1360) {
                int cc  = e / 340;
                int idx = e - cc*340;
                int r   = idx / 34;
                int c2  = idx - r*34;
                int gy = y0 - 1 + r;
                int gx = x0 - 1 + c2;
                bool ok = ((unsigned)gy < (unsigned)Hh) & ((unsigned)gx < (unsigned)Ww);
                const float* src = ok ? (inb + (size_t)(cb + cc)*HW + gy*Ww + gx) : inb;
                unsigned dst = smem_u32(&s_in[st][cc][r*35 + c2]);
                cp_async4(dst, src, ok ? 4 : 0);
            }
        }
        // weights: 4 channels x 288 ull = 1152 ull = 576 x 16B transfers
#pragma unroll
        for (int q = 0; q < 3; ++q) {
            int e = tid + q*256;
            if (e < 576) {
                int cc = e / 144, t = e - cc*144;   // t in 0..143, copies 2 ull
                const ull* src = wp + (size_t)(cb + cc)*288 + t*2;
                unsigned dst = smem_u32(&s_w[st][cc][t*2]);
                cp_async16(dst, src);
            }
        }
        cp_commit();
    };

    issue(0, 0);
    issue(1, 4);

    for (int s = 0; s < 16; ++s) {
        if (s >= 14) cp_wait<0>(); else cp_wait<1>();
        __syncthreads();     // also protects slot (s+2)%3 == (s-1)%3 overwrite
        if (s + 2 < 16) issue((s + 2) % 3, (s + 2) * 4);

        const int st = s % 3;
#pragma unroll
        for (int cc = 0; cc < 4; ++cc) {
#pragma unroll
            for (int r_in = 0; r_in < 4; ++r_in) {
                const int h = 2*rp + r_in;
                ull tp[6];
#pragma unroll
                for (int c = 0; c < 6; ++c) {
                    float t = s_in[st][cc][h*35 + xs + c];
                    tp[c] = pack2(t, t);
                }
#pragma unroll
                for (int L = 0; L < 2; ++L) {
                    if (r_in - L < 0 || r_in - L > 2) continue;
                    const int dy = r_in - L;
#pragma unroll
                    for (int dx = 0; dx < 3; ++dx) {
                        const int k = dy*3 + dx;
                        ulonglong2 w01 = *(const ulonglong2*)&s_w[st][cc][k*32 + wg*4];
                        ulonglong2 w23 = *(const ulonglong2*)&s_w[st][cc][k*32 + wg*4 + 2];
#pragma unroll
                        for (int px = 0; px < 4; ++px) {
                            ull a = tp[px + dx];
                            acc[0][L][px] = ffma2(a, w01.x, acc[0][L][px]);
                            acc[1][L][px] = ffma2(a, w01.y, acc[1][L][px]);
                            acc[2][L][px] = ffma2(a, w23.x, acc[2][L][px]);
                            acc[3][L][px] = ffma2(a, w23.y, acc[3][L][px]);
                        }
                    }
                }
            }
        }
    }

    float a = 0.f;
    if (PRELU) a = a_ptr[0];
    const int x = x0 + xs;
#pragma unroll
    for (int j = 0; j < 4; ++j) {
#pragma unroll
        for (int L = 0; L < 2; ++L) {
            const int y = y0 + 2*rp + L;
            float v0[4], v1[4];
#pragma unroll
            for (int px = 0; px < 4; ++px) {
                unpack2(acc[j][L][px], v0[px], v1[px]);
                if (PRELU) {
                    v0[px] = (v0[px] >= 0.f) ? v0[px] : a*v0[px];
                    v1[px] = (v1[px] >= 0.f) ? v1[px] : a*v1[px];
                }
            }
            size_t o0 = ((size_t)(b*Cc + co0 + 2*j)*Hh + y)*Ww + x;
            size_t o1 = o0 + (size_t)HW;
            float4 a0 = make_float4(v0[0], v0[1], v0[2], v0[3]);
            float4 b0 = make_float4(v1[0], v1[1], v1[2], v1[3]);
            if (RESID) {
                float4 r0 = *(const float4*)(resid + o0);
                float4 r1 = *(const float4*)(resid + o1);
                a0.x += r0.x; a0.y += r0.y; a0.z += r0.z; a0.w += r0.w;
                b0.x += r1.x; b0.y += r1.y; b0.z += r1.z; b0.w += r1.w;
            }
            *(float4*)(out + o0) = a0;
            *(float4*)(out + o1) = b0;
        }
    }
}

// ---------------------------------------------------------------------------
// FUSED: kg5 1x1 (64->576) + bias + dynamic joint-bilateral filter.
// 512 threads/block (16 warps), 1 px/thread, w5 staged in 147KB smem.
// ---------------------------------------------------------------------------
__global__ void __launch_bounds__(512, 1)
kgjbf_k(const float* __restrict__ y4,    // [B][64][HW]
        const float* __restrict__ w5,    // [576][64]
        const float* __restrict__ b5,    // [576]
        const float* __restrict__ img,   // [B][64][HW]
        float* __restrict__ out)         // [B][64][HW]
{
    extern __shared__ float smem[];
    float* s_w5 = smem;            // 36864 floats
    float* s_b5 = smem + 36864;    // 576 floats

    const int tid = threadIdx.x;
    const int b = blockIdx.y;
    const int p = blockIdx.x * 512 + tid;
    const int y = p >> 8;
    const int x = p & 255;

    {
        const float4* src = (const float4*)w5;
        float4* dst = (float4*)s_w5;
        for (int e = tid; e < 9216; e += 512) dst[e] = src[e];
        for (int e = tid; e < 576; e += 512) s_b5[e] = b5[e];
    }
    __syncthreads();

    ull yp[32];
    {
        const float* yb = y4 + (size_t)b*Cc*HW + p;
#pragma unroll
        for (int c2 = 0; c2 < 32; ++c2)
            yp[c2] = pack2(yb[(size_t)(2*c2)*HW], yb[(size_t)(2*c2+1)*HW]);
    }

    const float* ib = img + (size_t)b*Cc*HW;
    float* ob = out + (size_t)b*Cc*HW + p;

    for (int ci = 0; ci < 64; ++ci) {
        float acc = 0.f;
#pragma unroll
        for (int kk = 0; kk < 9; ++kk) {
            const int f = kk*64 + ci;
            const ulonglong2* wrow = (const ulonglong2*)(s_w5 + f*64);
            ull p0 = 0ULL, p1 = 0ULL, p2 = 0ULL, p3 = 0ULL;
#pragma unroll
            for (int c4 = 0; c4 < 16; c4 += 4) {
                ulonglong2 wv0 = wrow[c4  ];
                ulonglong2 wv1 = wrow[c4+1];
                ulonglong2 wv2 = wrow[c4+2];
                ulonglong2 wv3 = wrow[c4+3];
                p0 = ffma2(yp[2*c4  ], wv0.x, p0);
                p1 = ffma2(yp[2*c4+1], wv0.y, p1);
                p2 = ffma2(yp[2*c4+2], wv1.x, p2);
                p3 = ffma2(yp[2*c4+3], wv1.y, p3);
                p0 = ffma2(yp[2*c4+4], wv2.x, p0);
                p1 = ffma2(yp[2*c4+5], wv2.y, p1);
                p2 = ffma2(yp[2*c4+6], wv3.x, p2);
                p3 = ffma2(yp[2*c4+7], wv3.y, p3);
            }
            p0 = add2(p0, p1); p2 = add2(p2, p3); p0 = add2(p0, p2);
            float lo, hi; unpack2(p0, lo, hi);
            float bik = lo + hi + s_b5[f];

            int ch  = f / 9;
            int tap = f - ch*9;
            int dy  = tap / 3 - 1;
            int dx  = tap - (tap/3)*3 - 1;
            int yy = y + dy, xx = x + dx;
            float iv = 0.f;
            if ((unsigned)yy < (unsigned)Hh && (unsigned)xx < (unsigned)Ww)
                iv = ib[(size_t)ch*HW + yy*Ww + xx];
            acc = fmaf(bik, iv, acc);
        }
        ob[(size_t)ci*HW] = acc;
    }
}

// ---------------------------------------------------------------------------
extern "C" void kernel_launch(void* const* d_in, const int* in_sizes, int n_in,
                              void* d_out, int out_size)
{
    const float* image   = (const float*)d_in[0];
    const float* guidance= (const float*)d_in[1];
    const float* tensor_w= (const float*)d_in[2];
    const float* tensor_b= (const float*)d_in[3];
    const float* a_jbf   = (const float*)d_in[4];
    const float* kg_w1   = (const float*)d_in[5];
    const float* kg_b1   = (const float*)d_in[6];
    const float* kg_w2   = (const float*)d_in[7];
    const float* kg_b2   = (const float*)d_in[8];
    const float* kg_w3   = (const float*)d_in[9];
    const float* kg_b3   = (const float*)d_in[10];
    const float* kg_w4   = (const float*)d_in[11];
    const float* kg_b4   = (const float*)d_in[12];
    const float* kg_w5   = (const float*)d_in[13];
    const float* kg_b5   = (const float*)d_in[14];
    const float* a_kg    = (const float*)d_in[15];
    const float* jbf_w1  = (const float*)d_in[16];
    const float* jbf_b1  = (const float*)d_in[17];
    const float* jbf_w2  = (const float*)d_in[18];
    const float* jbf_b2  = (const float*)d_in[19];
    float* out = (float*)d_out;

    float *A, *Bb;
    ull* WP;
    cudaGetSymbolAddress((void**)&A,  g_A);
    cudaGetSymbolAddress((void**)&Bb, g_B);
    cudaGetSymbolAddress((void**)&WP, g_WP);

    static bool attr_set = false;
    if (!attr_set) {
        cudaFuncSetAttribute(kgjbf_k, cudaFuncAttributeMaxDynamicSharedMemorySize, 149760);
        attr_set = true;
    }

    dim3 blk(256);
    dim3 gf(64, 4, Bn);
    dim3 g3(Ww/32, Hh/8, Bn);
    dim3 gj(HW/512, Bn);

    // pack all six 3x3 conv weight tensors (layer order: kg1..kg4, jbf1, jbf2)
    pack_w_k<<<(110592 + 255)/256, blk>>>(kg_w1, kg_w2, kg_w3, kg_w4, jbf_w1, jbf_w2, WP);

    fuse1x1_k<<<gf, blk>>>(image, guidance, tensor_w, tensor_b, a_jbf, A);
    conv3x3_k<true,false><<<g3, blk>>>(A,  WP + 0*18432, kg_b1, a_kg, nullptr, Bb);
    conv3x3_k<true,false><<<g3, blk>>>(Bb, WP + 1*18432, kg_b2, a_kg, nullptr, A);
    conv3x3_k<true,false><<<g3, blk>>>(A,  WP + 2*18432, kg_b3, a_kg, nullptr, Bb);
    conv3x3_k<true,false><<<g3, blk>>>(Bb, WP + 3*18432, kg_b4, a_kg, nullptr, A);
    kgjbf_k<<<gj, dim3(512), 149760>>>(A, kg_w5, kg_b5, image, Bb);
    conv3x3_k<true,false><<<g3, blk>>>(Bb, WP + 4*18432, jbf_b1, a_jbf, nullptr, A);
    conv3x3_k<false,true><<<g3, blk>>>(A,  WP + 5*18432, jbf_b2, nullptr, image, out);
}

// round 8
// speedup vs baseline: 1.6162x; 1.0167x over previous
#include <cuda_runtime.h>
#include <cuda_bf16.h>
#include <cstddef>

#define Bn 2
#define Cc 64
#define Hh 256
#define Ww 256
#define HW (Hh*Ww)

typedef unsigned long long ull;

// -------- scratch (static device globals; no runtime alloc allowed) --------
__device__ float g_A[(size_t)Bn*Cc*HW];           // 33.5 MB
__device__ float g_B[(size_t)Bn*Cc*HW];           // 33.5 MB
__device__ ull   g_WP[6*64*9*32];                 // packed conv weights, 884KB

// ---------------- packed f32x2 helpers ----------------
__device__ __forceinline__ ull pack2(float lo, float hi) {
    ull r; asm("mov.b64 %0, {%1, %2};" : "=l"(r) : "f"(lo), "f"(hi)); return r;
}
__device__ __forceinline__ void unpack2(ull v, float& lo, float& hi) {
    asm("mov.b64 {%0, %1}, %2;" : "=f"(lo), "=f"(hi) : "l"(v));
}
__device__ __forceinline__ ull ffma2(ull a, ull b, ull c) {
    ull d; asm("fma.rn.f32x2 %0, %1, %2, %3;" : "=l"(d) : "l"(a), "l"(b), "l"(c)); return d;
}
__device__ __forceinline__ ull add2(ull a, ull b) {
    ull d; asm("add.rn.f32x2 %0, %1, %2;" : "=l"(d) : "l"(a), "l"(b)); return d;
}
__device__ __forceinline__ unsigned smem_u32(const void* p) {
    unsigned a;
    asm("{ .reg .u64 t; cvta.to.shared.u64 t, %1; cvt.u32.u64 %0, t; }"
        : "=r"(a) : "l"(p));
    return a;
}
__device__ __forceinline__ void cp_async4(unsigned dst, const void* src, int src_sz) {
    asm volatile("cp.async.ca.shared.global [%0], [%1], 4, %2;"
                 :: "r"(dst), "l"(src), "r"(src_sz) : "memory");
}
__device__ __forceinline__ void cp_async16(unsigned dst, const void* src) {
    asm volatile("cp.async.cg.shared.global [%0], [%1], 16;"
                 :: "r"(dst), "l"(src) : "memory");
}
__device__ __forceinline__ void cp_commit() {
    asm volatile("cp.async.commit_group;" ::: "memory");
}
template<int N>
__device__ __forceinline__ void cp_wait() {
    asm volatile("cp.async.wait_group %0;" :: "n"(N) : "memory");
}

// ---------------------------------------------------------------------------
// one-shot weight packer: wp[layer][ci][k][pr] = pack2(w[2pr][ci][k],
// w[2pr+1][ci][k]).  110592 elements total.
// ---------------------------------------------------------------------------
__global__ void pack_w_k(const float* __restrict__ w0, const float* __restrict__ w1,
                         const float* __restrict__ w2, const float* __restrict__ w3,
                         const float* __restrict__ w4, const float* __restrict__ w5,
                         ull* __restrict__ wp)
{
    int idx = blockIdx.x*256 + threadIdx.x;
    if (idx >= 110592) return;
    int layer = idx / 18432; int r = idx - layer*18432;
    int ci  = r / 288;       r -= ci*288;
    int k   = r / 32;        int pr = r - k*32;
    const float* w = (layer==0)?w0:(layer==1)?w1:(layer==2)?w2:
                     (layer==3)?w3:(layer==4)?w4:w5;
    int co0 = pr*2;
    wp[idx] = pack2(w[(co0*Cc + ci)*9 + k], w[((co0+1)*Cc + ci)*9 + k]);
}

// ---------------------------------------------------------------------------
// 1x1 fuse conv: concat(image, guidance) [128ch] -> 64ch, + bias, PReLU(a)
// ---------------------------------------------------------------------------
__global__ void __launch_bounds__(256, 2)
fuse1x1_k(const float* __restrict__ img,
          const float* __restrict__ gui,
          const float* __restrict__ w,     // [64][128]
          const float* __restrict__ bias,  // [64]
          const float* __restrict__ a_ptr,
          float* __restrict__ out)
{
    __shared__ ull s_wp[8*128];
    const int tid = threadIdx.x;
    const int tile = blockIdx.x;
    const int cog = blockIdx.y;
    const int b = blockIdx.z;

    for (int e = tid; e < 8*128; e += 256) {
        int jp = e >> 7, ci = e & 127;
        int co0 = cog*16 + 2*jp;
        s_wp[e] = pack2(w[co0*128 + ci], w[(co0+1)*128 + ci]);
    }
    __syncthreads();

    const int p0 = tile*1024 + tid;
    ull acc[8][4];
#pragma unroll
    for (int jp = 0; jp < 8; ++jp) {
        int co0 = cog*16 + 2*jp;
        ull bv = pack2(bias[co0], bias[co0+1]);
#pragma unroll
        for (int q = 0; q < 4; ++q) acc[jp][q] = bv;
    }

    const float* i0 = img + (size_t)b*Cc*HW + p0;
    const float* i1 = gui + (size_t)b*Cc*HW + p0;
#pragma unroll 2
    for (int ci = 0; ci < 64; ++ci) {
        const float* ic = i0 + (size_t)ci*HW;
        ull vp[4];
#pragma unroll
        for (int q = 0; q < 4; ++q) { float v = ic[q*256]; vp[q] = pack2(v, v); }
#pragma unroll
        for (int jp = 0; jp < 8; ++jp) {
            ull wv = s_wp[jp*128 + ci];
#pragma unroll
            for (int q = 0; q < 4; ++q) acc[jp][q] = ffma2(vp[q], wv, acc[jp][q]);
        }
    }
#pragma unroll 2
    for (int ci = 0; ci < 64; ++ci) {
        const float* ic = i1 + (size_t)ci*HW;
        ull vp[4];
#pragma unroll
        for (int q = 0; q < 4; ++q) { float v = ic[q*256]; vp[q] = pack2(v, v); }
#pragma unroll
        for (int jp = 0; jp < 8; ++jp) {
            ull wv = s_wp[jp*128 + 64 + ci];
#pragma unroll
            for (int q = 0; q < 4; ++q) acc[jp][q] = ffma2(vp[q], wv, acc[jp][q]);
        }
    }

    const float a = a_ptr[0];
#pragma unroll
    for (int jp = 0; jp < 8; ++jp) {
        int co0 = cog*16 + 2*jp;
        float* o0 = out + ((size_t)b*Cc + co0)*HW + p0;
        float* o1 = o0 + HW;
#pragma unroll
        for (int q = 0; q < 4; ++q) {
            float lo, hi; unpack2(acc[jp][q], lo, hi);
            lo = (lo >= 0.f) ? lo : a*lo;
            hi = (hi >= 0.f) ? hi : a*hi;
            o0[q*256] = lo;
            o1[q*256] = hi;
        }
    }
}

// ---------------------------------------------------------------------------
// 3x3 conv, 64->64, pad 1, optional PReLU, optional residual.
// grid (8, 32, B); block 256. Tile 32x8, ALL 64 out-ch per block.
// Thread: 2 adjacent rows x 4 px x 8 out-ch (4 co-pairs).
// cp.async 3-stage ring in DYNAMIC smem, 8 input channels/stage (8 barriers).
// Staging offsets hoisted into registers; weight copy is pure linear.
// ---------------------------------------------------------------------------
#define SIN_F   2800          // floats per stage: 8ch x 350
#define SW_U    2304          // ulls per stage:   8ch x 288
#define SIN_BYTES (SIN_F*4)   // 11200
#define SW_BYTES  (SW_U*8)    // 18432
#define CONV_SMEM (3*(SIN_BYTES + SW_BYTES))   // 88896

template<bool PRELU, bool RESID>
__global__ void __launch_bounds__(256, 2)
conv3x3_k(const float* __restrict__ in,
          const ull*   __restrict__ wp,    // packed [ci][k][32]
          const float* __restrict__ bias,
          const float* __restrict__ a_ptr,
          const float* __restrict__ resid,
          float* __restrict__ out)
{
    extern __shared__ __align__(16) char dyn_smem[];
    float* sin_f = (float*)dyn_smem;                       // 3 stages x 2800 f
    ull*   sw_u  = (ull*)(dyn_smem + 3*SIN_BYTES);         // 3 stages x 2304 ull
    const unsigned sin_base = smem_u32(sin_f);
    const unsigned sw_base  = smem_u32(sw_u);

    const int tid = threadIdx.x;
    const int x0  = blockIdx.x * 32;
    const int y0  = blockIdx.y * 8;
    const int b   = blockIdx.z;
    const int wg  = tid >> 5;            // 0..7 -> ch base wg*8
    const int lane = tid & 31;
    const int rp  = lane >> 3;           // 0..3 (row pair)
    const int xs  = (lane & 7) * 4;      // 0,4,...,28
    const int co0 = wg*8;

    ull acc[4][2][4];                    // [co-pair][row][px]
#pragma unroll
    for (int j = 0; j < 4; ++j) {
        ull bv = pack2(bias[co0 + 2*j], bias[co0 + 2*j + 1]);
#pragma unroll
        for (int L = 0; L < 2; ++L)
#pragma unroll
            for (int px = 0; px < 4; ++px) acc[j][L][px] = bv;
    }

    const float* inb = in + (size_t)b*Cc*HW;

    // ---- hoisted halo staging offsets (8 ch x 340 = 2720 elements) ----
    unsigned hdst[11];   // byte offset within one s_in stage
    int      hsrc[11];   // element offset within (cb..cb+7) channel block
    unsigned hmask = 0;  // in-bounds bits
#pragma unroll
    for (int q = 0; q < 11; ++q) {
        int e = tid + q*256;
        int cc  = e / 340;
        int idx = e - cc*340;
        int r   = idx / 34;
        int c2  = idx - r*34;
        int gy = y0 - 1 + r;
        int gx = x0 - 1 + c2;
        bool ok = (e < 2720) &&
                  ((unsigned)gy < (unsigned)Hh) && ((unsigned)gx < (unsigned)Ww);
        hdst[q] = (unsigned)(cc*350 + r*35 + c2) * 4u;
        hsrc[q] = ok ? (cc*HW + gy*Ww + gx) : 0;
        if (ok) hmask |= 1u << q;
    }

    auto issue = [&](int st, int cb) {
        const float* srcb = inb + (size_t)cb*HW;
        unsigned sbase = sin_base + st*SIN_BYTES;
#pragma unroll
        for (int q = 0; q < 11; ++q) {
            if (q < 10 || tid < 160) {   // e < 2720
                int ok4 = (hmask >> q) & 1;
                cp_async4(sbase + hdst[q], srcb + hsrc[q], ok4 << 2);
            }
        }
        // weights: linear copy, 1152 x 16B
        const ull* wsrc = wp + (size_t)cb*288;
        unsigned wbase = sw_base + st*SW_BYTES;
#pragma unroll
        for (int q = 0; q < 5; ++q) {
            int e = tid + q*256;
            if (q < 4 || tid < 128) {    // e < 1152
                cp_async16(wbase + (unsigned)e*16u, wsrc + 2*e);
            }
        }
        cp_commit();
    };

    issue(0, 0);
    issue(1, 8);

    for (int s = 0; s < 8; ++s) {
        if (s >= 6) cp_wait<0>(); else cp_wait<1>();
        __syncthreads();     // also protects ring slot (s+2)%3 overwrite
        if (s + 2 < 8) issue((s + 2) % 3, (s + 2) * 8);

        const int st = s % 3;
        const float* sif = sin_f + st*SIN_F;
        const ull*   swu = sw_u  + st*SW_U;
#pragma unroll
        for (int cc = 0; cc < 8; ++cc) {
#pragma unroll
            for (int r_in = 0; r_in < 4; ++r_in) {
                const int h = 2*rp + r_in;
                ull tp[6];
#pragma unroll
                for (int c = 0; c < 6; ++c) {
                    float t = sif[cc*350 + h*35 + xs + c];
                    tp[c] = pack2(t, t);
                }
#pragma unroll
                for (int L = 0; L < 2; ++L) {
                    if (r_in - L < 0 || r_in - L > 2) continue;
                    const int dy = r_in - L;
#pragma unroll
                    for (int dx = 0; dx < 3; ++dx) {
                        const int k = dy*3 + dx;
                        ulonglong2 w01 = *(const ulonglong2*)&swu[cc*288 + k*32 + wg*4];
                        ulonglong2 w23 = *(const ulonglong2*)&swu[cc*288 + k*32 + wg*4 + 2];
#pragma unroll
                        for (int px = 0; px < 4; ++px) {
                            ull a = tp[px + dx];
                            acc[0][L][px] = ffma2(a, w01.x, acc[0][L][px]);
                            acc[1][L][px] = ffma2(a, w01.y, acc[1][L][px]);
                            acc[2][L][px] = ffma2(a, w23.x, acc[2][L][px]);
                            acc[3][L][px] = ffma2(a, w23.y, acc[3][L][px]);
                        }
                    }
                }
            }
        }
    }

    float a = 0.f;
    if (PRELU) a = a_ptr[0];
    const int x = x0 + xs;
#pragma unroll
    for (int j = 0; j < 4; ++j) {
#pragma unroll
        for (int L = 0; L < 2; ++L) {
            const int y = y0 + 2*rp + L;
            float v0[4], v1[4];
#pragma unroll
            for (int px = 0; px < 4; ++px) {
                unpack2(acc[j][L][px], v0[px], v1[px]);
                if (PRELU) {
                    v0[px] = (v0[px] >= 0.f) ? v0[px] : a*v0[px];
                    v1[px] = (v1[px] >= 0.f) ? v1[px] : a*v1[px];
                }
            }
            size_t o0 = ((size_t)(b*Cc + co0 + 2*j)*Hh + y)*Ww + x;
            size_t o1 = o0 + (size_t)HW;
            float4 a0 = make_float4(v0[0], v0[1], v0[2], v0[3]);
            float4 b0 = make_float4(v1[0], v1[1], v1[2], v1[3]);
            if (RESID) {
                float4 r0 = *(const float4*)(resid + o0);
                float4 r1 = *(const float4*)(resid + o1);
                a0.x += r0.x; a0.y += r0.y; a0.z += r0.z; a0.w += r0.w;
                b0.x += r1.x; b0.y += r1.y; b0.z += r1.z; b0.w += r1.w;
            }
            *(float4*)(out + o0) = a0;
            *(float4*)(out + o1) = b0;
        }
    }
}

// ---------------------------------------------------------------------------
// FUSED: kg5 1x1 (64->576) + bias + dynamic joint-bilateral filter.
// 512 threads/block (16 warps), 1 px/thread, w5 staged in 147KB smem.
// ---------------------------------------------------------------------------
__global__ void __launch_bounds__(512, 1)
kgjbf_k(const float* __restrict__ y4,    // [B][64][HW]
        const float* __restrict__ w5,    // [576][64]
        const float* __restrict__ b5,    // [576]
        const float* __restrict__ img,   // [B][64][HW]
        float* __restrict__ out)         // [B][64][HW]
{
    extern __shared__ float smem[];
    float* s_w5 = smem;            // 36864 floats
    float* s_b5 = smem + 36864;    // 576 floats

    const int tid = threadIdx.x;
    const int b = blockIdx.y;
    const int p = blockIdx.x * 512 + tid;
    const int y = p >> 8;
    const int x = p & 255;

    {
        const float4* src = (const float4*)w5;
        float4* dst = (float4*)s_w5;
        for (int e = tid; e < 9216; e += 512) dst[e] = src[e];
        for (int e = tid; e < 576; e += 512) s_b5[e] = b5[e];
    }
    __syncthreads();

    ull yp[32];
    {
        const float* yb = y4 + (size_t)b*Cc*HW + p;
#pragma unroll
        for (int c2 = 0; c2 < 32; ++c2)
            yp[c2] = pack2(yb[(size_t)(2*c2)*HW], yb[(size_t)(2*c2+1)*HW]);
    }

    const float* ib = img + (size_t)b*Cc*HW;
    float* ob = out + (size_t)b*Cc*HW + p;

    for (int ci = 0; ci < 64; ++ci) {
        float acc = 0.f;
#pragma unroll
        for (int kk = 0; kk < 9; ++kk) {
            const int f = kk*64 + ci;
            const ulonglong2* wrow = (const ulonglong2*)(s_w5 + f*64);
            ull p0 = 0ULL, p1 = 0ULL, p2 = 0ULL, p3 = 0ULL;
#pragma unroll
            for (int c4 = 0; c4 < 16; c4 += 4) {
                ulonglong2 wv0 = wrow[c4  ];
                ulonglong2 wv1 = wrow[c4+1];
                ulonglong2 wv2 = wrow[c4+2];
                ulonglong2 wv3 = wrow[c4+3];
                p0 = ffma2(yp[2*c4  ], wv0.x, p0);
                p1 = ffma2(yp[2*c4+1], wv0.y, p1);
                p2 = ffma2(yp[2*c4+2], wv1.x, p2);
                p3 = ffma2(yp[2*c4+3], wv1.y, p3);
                p0 = ffma2(yp[2*c4+4], wv2.x, p0);
                p1 = ffma2(yp[2*c4+5], wv2.y, p1);
                p2 = ffma2(yp[2*c4+6], wv3.x, p2);
                p3 = ffma2(yp[2*c4+7], wv3.y, p3);
            }
            p0 = add2(p0, p1); p2 = add2(p2, p3); p0 = add2(p0, p2);
            float lo, hi; unpack2(p0, lo, hi);
            float bik = lo + hi + s_b5[f];

            int ch  = f / 9;
            int tap = f - ch*9;
            int dy  = tap / 3 - 1;
            int dx  = tap - (tap/3)*3 - 1;
            int yy = y + dy, xx = x + dx;
            float iv = 0.f;
            if ((unsigned)yy < (unsigned)Hh && (unsigned)xx < (unsigned)Ww)
                iv = ib[(size_t)ch*HW + yy*Ww + xx];
            acc = fmaf(bik, iv, acc);
        }
        ob[(size_t)ci*HW] = acc;
    }
}

// ---------------------------------------------------------------------------
extern "C" void kernel_launch(void* const* d_in, const int* in_sizes, int n_in,
                              void* d_out, int out_size)
{
    const float* image   = (const float*)d_in[0];
    const float* guidance= (const float*)d_in[1];
    const float* tensor_w= (const float*)d_in[2];
    const float* tensor_b= (const float*)d_in[3];
    const float* a_jbf   = (const float*)d_in[4];
    const float* kg_w1   = (const float*)d_in[5];
    const float* kg_b1   = (const float*)d_in[6];
    const float* kg_w2   = (const float*)d_in[7];
    const float* kg_b2   = (const float*)d_in[8];
    const float* kg_w3   = (const float*)d_in[9];
    const float* kg_b3   = (const float*)d_in[10];
    const float* kg_w4   = (const float*)d_in[11];
    const float* kg_b4   = (const float*)d_in[12];
    const float* kg_w5   = (const float*)d_in[13];
    const float* kg_b5   = (const float*)d_in[14];
    const float* a_kg    = (const float*)d_in[15];
    const float* jbf_w1  = (const float*)d_in[16];
    const float* jbf_b1  = (const float*)d_in[17];
    const float* jbf_w2  = (const float*)d_in[18];
    const float* jbf_b2  = (const float*)d_in[19];
    float* out = (float*)d_out;

    float *A, *Bb;
    ull* WP;
    cudaGetSymbolAddress((void**)&A,  g_A);
    cudaGetSymbolAddress((void**)&Bb, g_B);
    cudaGetSymbolAddress((void**)&WP, g_WP);

    static bool attr_set = false;
    if (!attr_set) {
        cudaFuncSetAttribute(kgjbf_k, cudaFuncAttributeMaxDynamicSharedMemorySize, 149760);
        cudaFuncSetAttribute(conv3x3_k<true,false>,
                             cudaFuncAttributeMaxDynamicSharedMemorySize, CONV_SMEM);
        cudaFuncSetAttribute(conv3x3_k<false,true>,
                             cudaFuncAttributeMaxDynamicSharedMemorySize, CONV_SMEM);
        attr_set = true;
    }

    dim3 blk(256);
    dim3 gf(64, 4, Bn);
    dim3 g3(Ww/32, Hh/8, Bn);
    dim3 gj(HW/512, Bn);

    // pack all six 3x3 conv weight tensors (layer order: kg1..kg4, jbf1, jbf2)
    pack_w_k<<<(110592 + 255)/256, blk>>>(kg_w1, kg_w2, kg_w3, kg_w4, jbf_w1, jbf_w2, WP);

    fuse1x1_k<<<gf, blk>>>(image, guidance, tensor_w, tensor_b, a_jbf, A);
    conv3x3_k<true,false><<<g3, blk, CONV_SMEM>>>(A,  WP + 0*18432, kg_b1, a_kg, nullptr, Bb);
    conv3x3_k<true,false><<<g3, blk, CONV_SMEM>>>(Bb, WP + 1*18432, kg_b2, a_kg, nullptr, A);
    conv3x3_k<true,false><<<g3, blk, CONV_SMEM>>>(A,  WP + 2*18432, kg_b3, a_kg, nullptr, Bb);
    conv3x3_k<true,false><<<g3, blk, CONV_SMEM>>>(Bb, WP + 3*18432, kg_b4, a_kg, nullptr, A);
    kgjbf_k<<<gj, dim3(512), 149760>>>(A, kg_w5, kg_b5, image, Bb);
    conv3x3_k<true,false><<<g3, blk, CONV_SMEM>>>(Bb, WP + 4*18432, jbf_b1, a_jbf, nullptr, A);
    conv3x3_k<false,true><<<g3, blk, CONV_SMEM>>>(A,  WP + 5*18432, jbf_b2, nullptr, image, out);
}

// round 9
// speedup vs baseline: 1.6390x; 1.0141x over previous
#include <cuda_runtime.h>
#include <cuda_bf16.h>
#include <cstddef>

#define Bn 2
#define Cc 64
#define Hh 256
#define Ww 256
#define HW (Hh*Ww)

typedef unsigned long long ull;

// -------- scratch (static device globals; no runtime alloc allowed) --------
__device__ float g_A[(size_t)Bn*Cc*HW];           // 33.5 MB
__device__ float g_B[(size_t)Bn*Cc*HW];           // 33.5 MB
__device__ ull   g_WP[6*64*9*32];                 // packed conv weights, 884KB

// ---------------- packed f32x2 helpers ----------------
__device__ __forceinline__ ull pack2(float lo, float hi) {
    ull r; asm("mov.b64 %0, {%1, %2};" : "=l"(r) : "f"(lo), "f"(hi)); return r;
}
__device__ __forceinline__ void unpack2(ull v, float& lo, float& hi) {
    asm("mov.b64 {%0, %1}, %2;" : "=f"(lo), "=f"(hi) : "l"(v));
}
__device__ __forceinline__ ull ffma2(ull a, ull b, ull c) {
    ull d; asm("fma.rn.f32x2 %0, %1, %2, %3;" : "=l"(d) : "l"(a), "l"(b), "l"(c)); return d;
}
__device__ __forceinline__ ull add2(ull a, ull b) {
    ull d; asm("add.rn.f32x2 %0, %1, %2;" : "=l"(d) : "l"(a), "l"(b)); return d;
}
__device__ __forceinline__ unsigned smem_u32(const void* p) {
    unsigned a;
    asm("{ .reg .u64 t; cvta.to.shared.u64 t, %1; cvt.u32.u64 %0, t; }"
        : "=r"(a) : "l"(p));
    return a;
}
__device__ __forceinline__ void cp_async4(unsigned dst, const void* src, int src_sz) {
    asm volatile("cp.async.ca.shared.global [%0], [%1], 4, %2;"
                 :: "r"(dst), "l"(src), "r"(src_sz) : "memory");
}
__device__ __forceinline__ void cp_async16(unsigned dst, const void* src) {
    asm volatile("cp.async.cg.shared.global [%0], [%1], 16;"
                 :: "r"(dst), "l"(src) : "memory");
}
__device__ __forceinline__ void cp_commit() {
    asm volatile("cp.async.commit_group;" ::: "memory");
}
template<int N>
__device__ __forceinline__ void cp_wait() {
    asm volatile("cp.async.wait_group %0;" :: "n"(N) : "memory");
}

// ---------------------------------------------------------------------------
// one-shot weight packer: wp[layer][ci][k][pr] = pack2(w[2pr][ci][k],
// w[2pr+1][ci][k]).  110592 elements total.
// ---------------------------------------------------------------------------
__global__ void pack_w_k(const float* __restrict__ w0, const float* __restrict__ w1,
                         const float* __restrict__ w2, const float* __restrict__ w3,
                         const float* __restrict__ w4, const float* __restrict__ w5,
                         ull* __restrict__ wp)
{
    int idx = blockIdx.x*256 + threadIdx.x;
    if (idx >= 110592) return;
    int layer = idx / 18432; int r = idx - layer*18432;
    int ci  = r / 288;       r -= ci*288;
    int k   = r / 32;        int pr = r - k*32;
    const float* w = (layer==0)?w0:(layer==1)?w1:(layer==2)?w2:
                     (layer==3)?w3:(layer==4)?w4:w5;
    int co0 = pr*2;
    wp[idx] = pack2(w[(co0*Cc + ci)*9 + k], w[((co0+1)*Cc + ci)*9 + k]);
}

// ---------------------------------------------------------------------------
// 1x1 fuse conv: concat(image, guidance) [128ch] -> 64ch, + bias, PReLU(a)
// grid (HW/512, 2, B); block 256. Thread: 2 px x 16 co-pairs (32 out-ch).
// Input read 2x total (was 4x).
// ---------------------------------------------------------------------------
__global__ void __launch_bounds__(256, 2)
fuse1x1_k(const float* __restrict__ img,
          const float* __restrict__ gui,
          const float* __restrict__ w,     // [64][128]
          const float* __restrict__ bias,  // [64]
          const float* __restrict__ a_ptr,
          float* __restrict__ out)
{
    __shared__ ull s_wp[16*128];
    const int tid = threadIdx.x;
    const int cog = blockIdx.y;          // 0/1 -> out-ch base cog*32
    const int b = blockIdx.z;

    for (int e = tid; e < 16*128; e += 256) {
        int jp = e >> 7, ci = e & 127;
        int co0 = cog*32 + 2*jp;
        s_wp[e] = pack2(w[co0*128 + ci], w[(co0+1)*128 + ci]);
    }
    __syncthreads();

    const int p0 = blockIdx.x*512 + tid;   // second pixel at p0+256
    ull acc[16][2];
#pragma unroll
    for (int jp = 0; jp < 16; ++jp) {
        int co0 = cog*32 + 2*jp;
        ull bv = pack2(bias[co0], bias[co0+1]);
        acc[jp][0] = bv; acc[jp][1] = bv;
    }

    const float* i0 = img + (size_t)b*Cc*HW + p0;
    const float* i1 = gui + (size_t)b*Cc*HW + p0;
#pragma unroll 2
    for (int ci = 0; ci < 64; ++ci) {
        const float* ic = i0 + (size_t)ci*HW;
        float v0 = ic[0], v1 = ic[256];
        ull vp0 = pack2(v0, v0), vp1 = pack2(v1, v1);
#pragma unroll
        for (int jp = 0; jp < 16; ++jp) {
            ull wv = s_wp[jp*128 + ci];
            acc[jp][0] = ffma2(vp0, wv, acc[jp][0]);
            acc[jp][1] = ffma2(vp1, wv, acc[jp][1]);
        }
    }
#pragma unroll 2
    for (int ci = 0; ci < 64; ++ci) {
        const float* ic = i1 + (size_t)ci*HW;
        float v0 = ic[0], v1 = ic[256];
        ull vp0 = pack2(v0, v0), vp1 = pack2(v1, v1);
#pragma unroll
        for (int jp = 0; jp < 16; ++jp) {
            ull wv = s_wp[jp*128 + 64 + ci];
            acc[jp][0] = ffma2(vp0, wv, acc[jp][0]);
            acc[jp][1] = ffma2(vp1, wv, acc[jp][1]);
        }
    }

    const float a = a_ptr[0];
#pragma unroll
    for (int jp = 0; jp < 16; ++jp) {
        int co0 = cog*32 + 2*jp;
        float* o0 = out + ((size_t)b*Cc + co0)*HW + p0;
        float* o1 = o0 + HW;
#pragma unroll
        for (int q = 0; q < 2; ++q) {
            float lo, hi; unpack2(acc[jp][q], lo, hi);
            lo = (lo >= 0.f) ? lo : a*lo;
            hi = (hi >= 0.f) ? hi : a*hi;
            o0[q*256] = lo;
            o1[q*256] = hi;
        }
    }
}

// ---------------------------------------------------------------------------
// 3x3 conv, 64->64, pad 1, optional PReLU, optional residual.
// grid (8, 32, B); block 256. Tile 32x8, ALL 64 out-ch per block.
// Thread: 2 adjacent rows x 4 px x 8 out-ch (4 co-pairs).
// cp.async 3-stage ring in DYNAMIC smem, 8 input channels/stage (8 barriers).
// ---------------------------------------------------------------------------
#define SIN_F   2800          // floats per stage: 8ch x 350
#define SW_U    2304          // ulls per stage:   8ch x 288
#define SIN_BYTES (SIN_F*4)   // 11200
#define SW_BYTES  (SW_U*8)    // 18432
#define CONV_SMEM (3*(SIN_BYTES + SW_BYTES))   // 88896

template<bool PRELU, bool RESID>
__global__ void __launch_bounds__(256, 2)
conv3x3_k(const float* __restrict__ in,
          const ull*   __restrict__ wp,    // packed [ci][k][32]
          const float* __restrict__ bias,
          const float* __restrict__ a_ptr,
          const float* __restrict__ resid,
          float* __restrict__ out)
{
    extern __shared__ __align__(16) char dyn_smem[];
    float* sin_f = (float*)dyn_smem;                       // 3 stages x 2800 f
    ull*   sw_u  = (ull*)(dyn_smem + 3*SIN_BYTES);         // 3 stages x 2304 ull
    const unsigned sin_base = smem_u32(sin_f);
    const unsigned sw_base  = smem_u32(sw_u);

    const int tid = threadIdx.x;
    const int x0  = blockIdx.x * 32;
    const int y0  = blockIdx.y * 8;
    const int b   = blockIdx.z;
    const int wg  = tid >> 5;            // 0..7 -> ch base wg*8
    const int lane = tid & 31;
    const int rp  = lane >> 3;           // 0..3 (row pair)
    const int xs  = (lane & 7) * 4;      // 0,4,...,28
    const int co0 = wg*8;

    ull acc[4][2][4];                    // [co-pair][row][px]
#pragma unroll
    for (int j = 0; j < 4; ++j) {
        ull bv = pack2(bias[co0 + 2*j], bias[co0 + 2*j + 1]);
#pragma unroll
        for (int L = 0; L < 2; ++L)
#pragma unroll
            for (int px = 0; px < 4; ++px) acc[j][L][px] = bv;
    }

    const float* inb = in + (size_t)b*Cc*HW;

    // ---- hoisted halo staging offsets (8 ch x 340 = 2720 elements) ----
    unsigned hdst[11];
    int      hsrc[11];
    unsigned hmask = 0;
#pragma unroll
    for (int q = 0; q < 11; ++q) {
        int e = tid + q*256;
        int cc  = e / 340;
        int idx = e - cc*340;
        int r   = idx / 34;
        int c2  = idx - r*34;
        int gy = y0 - 1 + r;
        int gx = x0 - 1 + c2;
        bool ok = (e < 2720) &&
                  ((unsigned)gy < (unsigned)Hh) && ((unsigned)gx < (unsigned)Ww);
        hdst[q] = (unsigned)(cc*350 + r*35 + c2) * 4u;
        hsrc[q] = ok ? (cc*HW + gy*Ww + gx) : 0;
        if (ok) hmask |= 1u << q;
    }

    auto issue = [&](int st, int cb) {
        const float* srcb = inb + (size_t)cb*HW;
        unsigned sbase = sin_base + st*SIN_BYTES;
#pragma unroll
        for (int q = 0; q < 11; ++q) {
            if (q < 10 || tid < 160) {
                int ok4 = (hmask >> q) & 1;
                cp_async4(sbase + hdst[q], srcb + hsrc[q], ok4 << 2);
            }
        }
        const ull* wsrc = wp + (size_t)cb*288;
        unsigned wbase = sw_base + st*SW_BYTES;
#pragma unroll
        for (int q = 0; q < 5; ++q) {
            int e = tid + q*256;
            if (q < 4 || tid < 128) {
                cp_async16(wbase + (unsigned)e*16u, wsrc + 2*e);
            }
        }
        cp_commit();
    };

    issue(0, 0);
    issue(1, 8);

    for (int s = 0; s < 8; ++s) {
        if (s >= 6) cp_wait<0>(); else cp_wait<1>();
        __syncthreads();
        if (s + 2 < 8) issue((s + 2) % 3, (s + 2) * 8);

        const int st = s % 3;
        const float* sif = sin_f + st*SIN_F;
        const ull*   swu = sw_u  + st*SW_U;
#pragma unroll
        for (int cc = 0; cc < 8; ++cc) {
#pragma unroll
            for (int r_in = 0; r_in < 4; ++r_in) {
                const int h = 2*rp + r_in;
                ull tp[6];
#pragma unroll
                for (int c = 0; c < 6; ++c) {
                    float t = sif[cc*350 + h*35 + xs + c];
                    tp[c] = pack2(t, t);
                }
#pragma unroll
                for (int L = 0; L < 2; ++L) {
                    if (r_in - L < 0 || r_in - L > 2) continue;
                    const int dy = r_in - L;
#pragma unroll
                    for (int dx = 0; dx < 3; ++dx) {
                        const int k = dy*3 + dx;
                        ulonglong2 w01 = *(const ulonglong2*)&swu[cc*288 + k*32 + wg*4];
                        ulonglong2 w23 = *(const ulonglong2*)&swu[cc*288 + k*32 + wg*4 + 2];
#pragma unroll
                        for (int px = 0; px < 4; ++px) {
                            ull a = tp[px + dx];
                            acc[0][L][px] = ffma2(a, w01.x, acc[0][L][px]);
                            acc[1][L][px] = ffma2(a, w01.y, acc[1][L][px]);
                            acc[2][L][px] = ffma2(a, w23.x, acc[2][L][px]);
                            acc[3][L][px] = ffma2(a, w23.y, acc[3][L][px]);
                        }
                    }
                }
            }
        }
    }

    float a = 0.f;
    if (PRELU) a = a_ptr[0];
    const int x = x0 + xs;
#pragma unroll
    for (int j = 0; j < 4; ++j) {
#pragma unroll
        for (int L = 0; L < 2; ++L) {
            const int y = y0 + 2*rp + L;
            float v0[4], v1[4];
#pragma unroll
            for (int px = 0; px < 4; ++px) {
                unpack2(acc[j][L][px], v0[px], v1[px]);
                if (PRELU) {
                    v0[px] = (v0[px] >= 0.f) ? v0[px] : a*v0[px];
                    v1[px] = (v1[px] >= 0.f) ? v1[px] : a*v1[px];
                }
            }
            size_t o0 = ((size_t)(b*Cc + co0 + 2*j)*Hh + y)*Ww + x;
            size_t o1 = o0 + (size_t)HW;
            float4 a0 = make_float4(v0[0], v0[1], v0[2], v0[3]);
            float4 b0 = make_float4(v1[0], v1[1], v1[2], v1[3]);
            if (RESID) {
                float4 r0 = *(const float4*)(resid + o0);
                float4 r1 = *(const float4*)(resid + o1);
                a0.x += r0.x; a0.y += r0.y; a0.z += r0.z; a0.w += r0.w;
                b0.x += r1.x; b0.y += r1.y; b0.z += r1.z; b0.w += r1.w;
            }
            *(float4*)(out + o0) = a0;
            *(float4*)(out + o1) = b0;
        }
    }
}

// ---------------------------------------------------------------------------
// FUSED: kg5 1x1 (64->576) + bias + dynamic joint-bilateral filter.
// ci-SPLIT: each block computes 32 of the 64 output channels; stages only
// the 288 needed w5 rows (73.7KB) -> 2 CTAs/SM. 256 thr, 1 px/thread.
// grid (HW/256, 2, B).
// ---------------------------------------------------------------------------
#define KGJ_SMEM (288*64*4 + 288*4)   // 73728 + 1152 = 74880

__global__ void __launch_bounds__(256, 2)
kgjbf_k(const float* __restrict__ y4,    // [B][64][HW]
        const float* __restrict__ w5,    // [576][64]
        const float* __restrict__ b5,    // [576]
        const float* __restrict__ img,   // [B][64][HW]
        float* __restrict__ out)         // [B][64][HW]
{
    extern __shared__ float smem[];
    float* s_w5 = smem;            // 288 rows x 64 floats (row kk*32+j -> f)
    float* s_b5 = smem + 288*64;   // 288 floats

    const int tid = threadIdx.x;
    const int cig = blockIdx.y;    // 0/1 -> ci base cig*32
    const int ci0 = cig*32;
    const int b = blockIdx.z;
    const int p = blockIdx.x * 256 + tid;
    const int y = p >> 8;
    const int x = p & 255;

    {
        // rows: local row = kk*32 + j  <->  global f = kk*64 + ci0 + j
        float4* dst = (float4*)s_w5;
        for (int e = tid; e < 288*16; e += 256) {
            int row = e >> 4, q = e & 15;
            int f = ((row >> 5) << 6) + ci0 + (row & 31);
            dst[e] = ((const float4*)(w5 + (size_t)f*64))[q];
        }
        for (int e = tid; e < 288; e += 256)
            s_b5[e] = b5[((e >> 5) << 6) + ci0 + (e & 31)];
    }
    __syncthreads();

    ull yp[32];
    {
        const float* yb = y4 + (size_t)b*Cc*HW + p;
#pragma unroll
        for (int c2 = 0; c2 < 32; ++c2)
            yp[c2] = pack2(yb[(size_t)(2*c2)*HW], yb[(size_t)(2*c2+1)*HW]);
    }

    const float* ib = img + (size_t)b*Cc*HW;
    float* ob = out + ((size_t)b*Cc + ci0)*HW + p;

    for (int j = 0; j < 32; ++j) {
        const int ci = ci0 + j;
        float acc = 0.f;
#pragma unroll
        for (int kk = 0; kk < 9; ++kk) {
            const int f = kk*64 + ci;
            const int row = kk*32 + j;
            const ulonglong2* wrow = (const ulonglong2*)(s_w5 + row*64);
            ull p0 = 0ULL, p1 = 0ULL, p2 = 0ULL, p3 = 0ULL;
#pragma unroll
            for (int c4 = 0; c4 < 16; c4 += 4) {
                ulonglong2 wv0 = wrow[c4  ];
                ulonglong2 wv1 = wrow[c4+1];
                ulonglong2 wv2 = wrow[c4+2];
                ulonglong2 wv3 = wrow[c4+3];
                p0 = ffma2(yp[2*c4  ], wv0.x, p0);
                p1 = ffma2(yp[2*c4+1], wv0.y, p1);
                p2 = ffma2(yp[2*c4+2], wv1.x, p2);
                p3 = ffma2(yp[2*c4+3], wv1.y, p3);
                p0 = ffma2(yp[2*c4+4], wv2.x, p0);
                p1 = ffma2(yp[2*c4+5], wv2.y, p1);
                p2 = ffma2(yp[2*c4+6], wv3.x, p2);
                p3 = ffma2(yp[2*c4+7], wv3.y, p3);
            }
            p0 = add2(p0, p1); p2 = add2(p2, p3); p0 = add2(p0, p2);
            float lo, hi; unpack2(p0, lo, hi);
            float bik = lo + hi + s_b5[row];

            int ch  = f / 9;
            int tap = f - ch*9;
            int dy  = tap / 3 - 1;
            int dx  = tap - (tap/3)*3 - 1;
            int yy = y + dy, xx = x + dx;
            float iv = 0.f;
            if ((unsigned)yy < (unsigned)Hh && (unsigned)xx < (unsigned)Ww)
                iv = ib[(size_t)ch*HW + yy*Ww + xx];
            acc = fmaf(bik, iv, acc);
        }
        ob[(size_t)j*HW] = acc;
    }
}

// ---------------------------------------------------------------------------
extern "C" void kernel_launch(void* const* d_in, const int* in_sizes, int n_in,
                              void* d_out, int out_size)
{
    const float* image   = (const float*)d_in[0];
    const float* guidance= (const float*)d_in[1];
    const float* tensor_w= (const float*)d_in[2];
    const float* tensor_b= (const float*)d_in[3];
    const float* a_jbf   = (const float*)d_in[4];
    const float* kg_w1   = (const float*)d_in[5];
    const float* kg_b1   = (const float*)d_in[6];
    const float* kg_w2   = (const float*)d_in[7];
    const float* kg_b2   = (const float*)d_in[8];
    const float* kg_w3   = (const float*)d_in[9];
    const float* kg_b3   = (const float*)d_in[10];
    const float* kg_w4   = (const float*)d_in[11];
    const float* kg_b4   = (const float*)d_in[12];
    const float* kg_w5   = (const float*)d_in[13];
    const float* kg_b5   = (const float*)d_in[14];
    const float* a_kg    = (const float*)d_in[15];
    const float* jbf_w1  = (const float*)d_in[16];
    const float* jbf_b1  = (const float*)d_in[17];
    const float* jbf_w2  = (const float*)d_in[18];
    const float* jbf_b2  = (const float*)d_in[19];
    float* out = (float*)d_out;

    float *A, *Bb;
    ull* WP;
    cudaGetSymbolAddress((void**)&A,  g_A);
    cudaGetSymbolAddress((void**)&Bb, g_B);
    cudaGetSymbolAddress((void**)&WP, g_WP);

    static bool attr_set = false;
    if (!attr_set) {
        cudaFuncSetAttribute(kgjbf_k, cudaFuncAttributeMaxDynamicSharedMemorySize, KGJ_SMEM);
        cudaFuncSetAttribute(conv3x3_k<true,false>,
                             cudaFuncAttributeMaxDynamicSharedMemorySize, CONV_SMEM);
        cudaFuncSetAttribute(conv3x3_k<false,true>,
                             cudaFuncAttributeMaxDynamicSharedMemorySize, CONV_SMEM);
        attr_set = true;
    }

    dim3 blk(256);
    dim3 gf(HW/512, 2, Bn);
    dim3 g3(Ww/32, Hh/8, Bn);
    dim3 gj(HW/256, 2, Bn);

    // pack all six 3x3 conv weight tensors (layer order: kg1..kg4, jbf1, jbf2)
    pack_w_k<<<(110592 + 255)/256, blk>>>(kg_w1, kg_w2, kg_w3, kg_w4, jbf_w1, jbf_w2, WP);

    fuse1x1_k<<<gf, blk>>>(image, guidance, tensor_w, tensor_b, a_jbf, A);
    conv3x3_k<true,false><<<g3, blk, CONV_SMEM>>>(A,  WP + 0*18432, kg_b1, a_kg, nullptr, Bb);
    conv3x3_k<true,false><<<g3, blk, CONV_SMEM>>>(Bb, WP + 1*18432, kg_b2, a_kg, nullptr, A);
    conv3x3_k<true,false><<<g3, blk, CONV_SMEM>>>(A,  WP + 2*18432, kg_b3, a_kg, nullptr, Bb);
    conv3x3_k<true,false><<<g3, blk, CONV_SMEM>>>(Bb, WP + 3*18432, kg_b4, a_kg, nullptr, A);
    kgjbf_k<<<gj, blk, KGJ_SMEM>>>(A, kg_w5, kg_b5, image, Bb);
    conv3x3_k<true,false><<<g3, blk, CONV_SMEM>>>(Bb, WP + 4*18432, jbf_b1, a_jbf, nullptr, A);
    conv3x3_k<false,true><<<g3, blk, CONV_SMEM>>>(A,  WP + 5*18432, jbf_b2, nullptr, image, out);
}

// round 10
// speedup vs baseline: 1.6417x; 1.0016x over previous
#include <cuda_runtime.h>
#include <cuda_bf16.h>
#include <cstddef>

#define Bn 2
#define Cc 64
#define Hh 256
#define Ww 256
#define HW (Hh*Ww)

typedef unsigned long long ull;

// -------- scratch (static device globals; no runtime alloc allowed) --------
__device__ float g_A[(size_t)Bn*Cc*HW];           // 33.5 MB
__device__ float g_B[(size_t)Bn*Cc*HW];           // 33.5 MB
__device__ ull   g_WP[6*64*9*32];                 // packed conv weights, 884KB

// ---------------- packed f32x2 helpers ----------------
__device__ __forceinline__ ull pack2(float lo, float hi) {
    ull r; asm("mov.b64 %0, {%1, %2};" : "=l"(r) : "f"(lo), "f"(hi)); return r;
}
__device__ __forceinline__ void unpack2(ull v, float& lo, float& hi) {
    asm("mov.b64 {%0, %1}, %2;" : "=f"(lo), "=f"(hi) : "l"(v));
}
__device__ __forceinline__ ull ffma2(ull a, ull b, ull c) {
    ull d; asm("fma.rn.f32x2 %0, %1, %2, %3;" : "=l"(d) : "l"(a), "l"(b), "l"(c)); return d;
}
__device__ __forceinline__ ull add2(ull a, ull b) {
    ull d; asm("add.rn.f32x2 %0, %1, %2;" : "=l"(d) : "l"(a), "l"(b)); return d;
}
__device__ __forceinline__ unsigned smem_u32(const void* p) {
    unsigned a;
    asm("{ .reg .u64 t; cvta.to.shared.u64 t, %1; cvt.u32.u64 %0, t; }"
        : "=r"(a) : "l"(p));
    return a;
}
__device__ __forceinline__ void cp_async4(unsigned dst, const void* src, int src_sz) {
    asm volatile("cp.async.ca.shared.global [%0], [%1], 4, %2;"
                 :: "r"(dst), "l"(src), "r"(src_sz) : "memory");
}
__device__ __forceinline__ void cp_async16(unsigned dst, const void* src) {
    asm volatile("cp.async.cg.shared.global [%0], [%1], 16;"
                 :: "r"(dst), "l"(src) : "memory");
}
__device__ __forceinline__ void cp_commit() {
    asm volatile("cp.async.commit_group;" ::: "memory");
}
template<int N>
__device__ __forceinline__ void cp_wait() {
    asm volatile("cp.async.wait_group %0;" :: "n"(N) : "memory");
}

// ---------------------------------------------------------------------------
// one-shot weight packer: wp[layer][ci][k][pr] = pack2(w[2pr][ci][k],
// w[2pr+1][ci][k]).  110592 elements total.
// ---------------------------------------------------------------------------
__global__ void pack_w_k(const float* __restrict__ w0, const float* __restrict__ w1,
                         const float* __restrict__ w2, const float* __restrict__ w3,
                         const float* __restrict__ w4, const float* __restrict__ w5,
                         ull* __restrict__ wp)
{
    int idx = blockIdx.x*256 + threadIdx.x;
    if (idx >= 110592) return;
    int layer = idx / 18432; int r = idx - layer*18432;
    int ci  = r / 288;       r -= ci*288;
    int k   = r / 32;        int pr = r - k*32;
    const float* w = (layer==0)?w0:(layer==1)?w1:(layer==2)?w2:
                     (layer==3)?w3:(layer==4)?w4:w5;
    int co0 = pr*2;
    wp[idx] = pack2(w[(co0*Cc + ci)*9 + k], w[((co0+1)*Cc + ci)*9 + k]);
}

// ---------------------------------------------------------------------------
// 1x1 fuse conv: concat(image, guidance) [128ch] -> 64ch, + bias, PReLU(a)
// grid (HW/512, 2, B); block 256. Thread: 2 px x 16 co-pairs (32 out-ch).
// Input read 2x total (was 4x).
// ---------------------------------------------------------------------------
__global__ void __launch_bounds__(256, 2)
fuse1x1_k(const float* __restrict__ img,
          const float* __restrict__ gui,
          const float* __restrict__ w,     // [64][128]
          const float* __restrict__ bias,  // [64]
          const float* __restrict__ a_ptr,
          float* __restrict__ out)
{
    __shared__ ull s_wp[16*128];
    const int tid = threadIdx.x;
    const int cog = blockIdx.y;          // 0/1 -> out-ch base cog*32
    const int b = blockIdx.z;

    for (int e = tid; e < 16*128; e += 256) {
        int jp = e >> 7, ci = e & 127;
        int co0 = cog*32 + 2*jp;
        s_wp[e] = pack2(w[co0*128 + ci], w[(co0+1)*128 + ci]);
    }
    __syncthreads();

    const int p0 = blockIdx.x*512 + tid;   // second pixel at p0+256
    ull acc[16][2];
#pragma unroll
    for (int jp = 0; jp < 16; ++jp) {
        int co0 = cog*32 + 2*jp;
        ull bv = pack2(bias[co0], bias[co0+1]);
        acc[jp][0] = bv; acc[jp][1] = bv;
    }

    const float* i0 = img + (size_t)b*Cc*HW + p0;
    const float* i1 = gui + (size_t)b*Cc*HW + p0;
#pragma unroll 2
    for (int ci = 0; ci < 64; ++ci) {
        const float* ic = i0 + (size_t)ci*HW;
        float v0 = ic[0], v1 = ic[256];
        ull vp0 = pack2(v0, v0), vp1 = pack2(v1, v1);
#pragma unroll
        for (int jp = 0; jp < 16; ++jp) {
            ull wv = s_wp[jp*128 + ci];
            acc[jp][0] = ffma2(vp0, wv, acc[jp][0]);
            acc[jp][1] = ffma2(vp1, wv, acc[jp][1]);
        }
    }
#pragma unroll 2
    for (int ci = 0; ci < 64; ++ci) {
        const float* ic = i1 + (size_t)ci*HW;
        float v0 = ic[0], v1 = ic[256];
        ull vp0 = pack2(v0, v0), vp1 = pack2(v1, v1);
#pragma unroll
        for (int jp = 0; jp < 16; ++jp) {
            ull wv = s_wp[jp*128 + 64 + ci];
            acc[jp][0] = ffma2(vp0, wv, acc[jp][0]);
            acc[jp][1] = ffma2(vp1, wv, acc[jp][1]);
        }
    }

    const float a = a_ptr[0];
#pragma unroll
    for (int jp = 0; jp < 16; ++jp) {
        int co0 = cog*32 + 2*jp;
        float* o0 = out + ((size_t)b*Cc + co0)*HW + p0;
        float* o1 = o0 + HW;
#pragma unroll
        for (int q = 0; q < 2; ++q) {
            float lo, hi; unpack2(acc[jp][q], lo, hi);
            lo = (lo >= 0.f) ? lo : a*lo;
            hi = (hi >= 0.f) ? hi : a*hi;
            o0[q*256] = lo;
            o1[q*256] = hi;
        }
    }
}

// ---------------------------------------------------------------------------
// 3x3 conv, 64->64, pad 1, optional PReLU, optional residual.
// grid (8, 32, B); block 256. Tile 32x8, ALL 64 out-ch per block.
// Thread: 2 adjacent rows x 4 px x 8 out-ch (4 co-pairs).
// cp.async 3-stage ring in DYNAMIC smem, 8 input channels/stage (8 barriers).
// ---------------------------------------------------------------------------
#define SIN_F   2800          // floats per stage: 8ch x 350
#define SW_U    2304          // ulls per stage:   8ch x 288
#define SIN_BYTES (SIN_F*4)   // 11200
#define SW_BYTES  (SW_U*8)    // 18432
#define CONV_SMEM (3*(SIN_BYTES + SW_BYTES))   // 88896

template<bool PRELU, bool RESID>
__global__ void __launch_bounds__(256, 2)
conv3x3_k(const float* __restrict__ in,
          const ull*   __restrict__ wp,    // packed [ci][k][32]
          const float* __restrict__ bias,
          const float* __restrict__ a_ptr,
          const float* __restrict__ resid,
          float* __restrict__ out)
{
    extern __shared__ __align__(16) char dyn_smem[];
    float* sin_f = (float*)dyn_smem;                       // 3 stages x 2800 f
    ull*   sw_u  = (ull*)(dyn_smem + 3*SIN_BYTES);         // 3 stages x 2304 ull
    const unsigned sin_base = smem_u32(sin_f);
    const unsigned sw_base  = smem_u32(sw_u);

    const int tid = threadIdx.x;
    const int x0  = blockIdx.x * 32;
    const int y0  = blockIdx.y * 8;
    const int b   = blockIdx.z;
    const int wg  = tid >> 5;            // 0..7 -> ch base wg*8
    const int lane = tid & 31;
    const int rp  = lane >> 3;           // 0..3 (row pair)
    const int xs  = (lane & 7) * 4;      // 0,4,...,28
    const int co0 = wg*8;

    ull acc[4][2][4];                    // [co-pair][row][px]
#pragma unroll
    for (int j = 0; j < 4; ++j) {
        ull bv = pack2(bias[co0 + 2*j], bias[co0 + 2*j + 1]);
#pragma unroll
        for (int L = 0; L < 2; ++L)
#pragma unroll
            for (int px = 0; px < 4; ++px) acc[j][L][px] = bv;
    }

    const float* inb = in + (size_t)b*Cc*HW;

    // ---- hoisted halo staging offsets (8 ch x 340 = 2720 elements) ----
    unsigned hdst[11];
    int      hsrc[11];
    unsigned hmask = 0;
#pragma unroll
    for (int q = 0; q < 11; ++q) {
        int e = tid + q*256;
        int cc  = e / 340;
        int idx = e - cc*340;
        int r   = idx / 34;
        int c2  = idx - r*34;
        int gy = y0 - 1 + r;
        int gx = x0 - 1 + c2;
        bool ok = (e < 2720) &&
                  ((unsigned)gy < (unsigned)Hh) && ((unsigned)gx < (unsigned)Ww);
        hdst[q] = (unsigned)(cc*350 + r*35 + c2) * 4u;
        hsrc[q] = ok ? (cc*HW + gy*Ww + gx) : 0;
        if (ok) hmask |= 1u << q;
    }

    auto issue = [&](int st, int cb) {
        const float* srcb = inb + (size_t)cb*HW;
        unsigned sbase = sin_base + st*SIN_BYTES;
#pragma unroll
        for (int q = 0; q < 11; ++q) {
            if (q < 10 || tid < 160) {
                int ok4 = (hmask >> q) & 1;
                cp_async4(sbase + hdst[q], srcb + hsrc[q], ok4 << 2);
            }
        }
        const ull* wsrc = wp + (size_t)cb*288;
        unsigned wbase = sw_base + st*SW_BYTES;
#pragma unroll
        for (int q = 0; q < 5; ++q) {
            int e = tid + q*256;
            if (q < 4 || tid < 128) {
                cp_async16(wbase + (unsigned)e*16u, wsrc + 2*e);
            }
        }
        cp_commit();
    };

    issue(0, 0);
    issue(1, 8);

    for (int s = 0; s < 8; ++s) {
        if (s >= 6) cp_wait<0>(); else cp_wait<1>();
        __syncthreads();
        if (s + 2 < 8) issue((s + 2) % 3, (s + 2) * 8);

        const int st = s % 3;
        const float* sif = sin_f + st*SIN_F;
        const ull*   swu = sw_u  + st*SW_U;
#pragma unroll
        for (int cc = 0; cc < 8; ++cc) {
#pragma unroll
            for (int r_in = 0; r_in < 4; ++r_in) {
                const int h = 2*rp + r_in;
                ull tp[6];
#pragma unroll
                for (int c = 0; c < 6; ++c) {
                    float t = sif[cc*350 + h*35 + xs + c];
                    tp[c] = pack2(t, t);
                }
#pragma unroll
                for (int L = 0; L < 2; ++L) {
                    if (r_in - L < 0 || r_in - L > 2) continue;
                    const int dy = r_in - L;
#pragma unroll
                    for (int dx = 0; dx < 3; ++dx) {
                        const int k = dy*3 + dx;
                        ulonglong2 w01 = *(const ulonglong2*)&swu[cc*288 + k*32 + wg*4];
                        ulonglong2 w23 = *(const ulonglong2*)&swu[cc*288 + k*32 + wg*4 + 2];
#pragma unroll
                        for (int px = 0; px < 4; ++px) {
                            ull a = tp[px + dx];
                            acc[0][L][px] = ffma2(a, w01.x, acc[0][L][px]);
                            acc[1][L][px] = ffma2(a, w01.y, acc[1][L][px]);
                            acc[2][L][px] = ffma2(a, w23.x, acc[2][L][px]);
                            acc[3][L][px] = ffma2(a, w23.y, acc[3][L][px]);
                        }
                    }
                }
            }
        }
    }

    float a = 0.f;
    if (PRELU) a = a_ptr[0];
    const int x = x0 + xs;
#pragma unroll
    for (int j = 0; j < 4; ++j) {
#pragma unroll
        for (int L = 0; L < 2; ++L) {
            const int y = y0 + 2*rp + L;
            float v0[4], v1[4];
#pragma unroll
            for (int px = 0; px < 4; ++px) {
                unpack2(acc[j][L][px], v0[px], v1[px]);
                if (PRELU) {
                    v0[px] = (v0[px] >= 0.f) ? v0[px] : a*v0[px];
                    v1[px] = (v1[px] >= 0.f) ? v1[px] : a*v1[px];
                }
            }
            size_t o0 = ((size_t)(b*Cc + co0 + 2*j)*Hh + y)*Ww + x;
            size_t o1 = o0 + (size_t)HW;
            float4 a0 = make_float4(v0[0], v0[1], v0[2], v0[3]);
            float4 b0 = make_float4(v1[0], v1[1], v1[2], v1[3]);
            if (RESID) {
                float4 r0 = *(const float4*)(resid + o0);
                float4 r1 = *(const float4*)(resid + o1);
                a0.x += r0.x; a0.y += r0.y; a0.z += r0.z; a0.w += r0.w;
                b0.x += r1.x; b0.y += r1.y; b0.z += r1.z; b0.w += r1.w;
            }
            *(float4*)(out + o0) = a0;
            *(float4*)(out + o1) = b0;
        }
    }
}

// ---------------------------------------------------------------------------
// FUSED: kg5 1x1 (64->576) + bias + dynamic joint-bilateral filter.
// ci-SPLIT: each block computes 32 of the 64 output channels; stages only
// the 288 needed w5 rows (73.7KB) -> 2 CTAs/SM. 256 thr, 1 px/thread.
// grid (HW/256, 2, B).
// ---------------------------------------------------------------------------
#define KGJ_SMEM (288*64*4 + 288*4)   // 73728 + 1152 = 74880

__global__ void __launch_bounds__(256, 2)
kgjbf_k(const float* __restrict__ y4,    // [B][64][HW]
        const float* __restrict__ w5,    // [576][64]
        const float* __restrict__ b5,    // [576]
        const float* __restrict__ img,   // [B][64][HW]
        float* __restrict__ out)         // [B][64][HW]
{
    extern __shared__ float smem[];
    float* s_w5 = smem;            // 288 rows x 64 floats (row kk*32+j -> f)
    float* s_b5 = smem + 288*64;   // 288 floats

    const int tid = threadIdx.x;
    const int cig = blockIdx.y;    // 0/1 -> ci base cig*32
    const int ci0 = cig*32;
    const int b = blockIdx.z;
    const int p = blockIdx.x * 256 + tid;
    const int y = p >> 8;
    const int x = p & 255;

    {
        // rows: local row = kk*32 + j  <->  global f = kk*64 + ci0 + j
        float4* dst = (float4*)s_w5;
        for (int e = tid; e < 288*16; e += 256) {
            int row = e >> 4, q = e & 15;
            int f = ((row >> 5) << 6) + ci0 + (row & 31);
            dst[e] = ((const float4*)(w5 + (size_t)f*64))[q];
        }
        for (int e = tid; e < 288; e += 256)
            s_b5[e] = b5[((e >> 5) << 6) + ci0 + (e & 31)];
    }
    __syncthreads();

    ull yp[32];
    {
        const float* yb = y4 + (size_t)b*Cc*HW + p;
#pragma unroll
        for (int c2 = 0; c2 < 32; ++c2)
            yp[c2] = pack2(yb[(size_t)(2*c2)*HW], yb[(size_t)(2*c2+1)*HW]);
    }

    const float* ib = img + (size_t)b*Cc*HW;
    float* ob = out + ((size_t)b*Cc + ci0)*HW + p;

    for (int j = 0; j < 32; ++j) {
        const int ci = ci0 + j;
        float acc = 0.f;
#pragma unroll
        for (int kk = 0; kk < 9; ++kk) {
            const int f = kk*64 + ci;
            const int row = kk*32 + j;
            const ulonglong2* wrow = (const ulonglong2*)(s_w5 + row*64);
            ull p0 = 0ULL, p1 = 0ULL, p2 = 0ULL, p3 = 0ULL;
#pragma unroll
            for (int c4 = 0; c4 < 16; c4 += 4) {
                ulonglong2 wv0 = wrow[c4  ];
                ulonglong2 wv1 = wrow[c4+1];
                ulonglong2 wv2 = wrow[c4+2];
                ulonglong2 wv3 = wrow[c4+3];
                p0 = ffma2(yp[2*c4  ], wv0.x, p0);
                p1 = ffma2(yp[2*c4+1], wv0.y, p1);
                p2 = ffma2(yp[2*c4+2], wv1.x, p2);
                p3 = ffma2(yp[2*c4+3], wv1.y, p3);
                p0 = ffma2(yp[2*c4+4], wv2.x, p0);
                p1 = ffma2(yp[2*c4+5], wv2.y, p1);
                p2 = ffma2(yp[2*c4+6], wv3.x, p2);
                p3 = ffma2(yp[2*c4+7], wv3.y, p3);
            }
            p0 = add2(p0, p1); p2 = add2(p2, p3); p0 = add2(p0, p2);
            float lo, hi; unpack2(p0, lo, hi);
            float bik = lo + hi + s_b5[row];

            int ch  = f / 9;
            int tap = f - ch*9;
            int dy  = tap / 3 - 1;
            int dx  = tap - (tap/3)*3 - 1;
            int yy = y + dy, xx = x + dx;
            float iv = 0.f;
            if ((unsigned)yy < (unsigned)Hh && (unsigned)xx < (unsigned)Ww)
                iv = ib[(size_t)ch*HW + yy*Ww + xx];
            acc = fmaf(bik, iv, acc);
        }
        ob[(size_t)j*HW] = acc;
    }
}

// ---------------------------------------------------------------------------
extern "C" void kernel_launch(void* const* d_in, const int* in_sizes, int n_in,
                              void* d_out, int out_size)
{
    const float* image   = (const float*)d_in[0];
    const float* guidance= (const float*)d_in[1];
    const float* tensor_w= (const float*)d_in[2];
    const float* tensor_b= (const float*)d_in[3];
    const float* a_jbf   = (const float*)d_in[4];
    const float* kg_w1   = (const float*)d_in[5];
    const float* kg_b1   = (const float*)d_in[6];
    const float* kg_w2   = (const float*)d_in[7];
    const float* kg_b2   = (const float*)d_in[8];
    const float* kg_w3   = (const float*)d_in[9];
    const float* kg_b3   = (const float*)d_in[10];
    const float* kg_w4   = (const float*)d_in[11];
    const float* kg_b4   = (const float*)d_in[12];
    const float* kg_w5   = (const float*)d_in[13];
    const float* kg_b5   = (const float*)d_in[14];
    const float* a_kg    = (const float*)d_in[15];
    const float* jbf_w1  = (const float*)d_in[16];
    const float* jbf_b1  = (const float*)d_in[17];
    const float* jbf_w2  = (const float*)d_in[18];
    const float* jbf_b2  = (const float*)d_in[19];
    float* out = (float*)d_out;

    float *A, *Bb;
    ull* WP;
    cudaGetSymbolAddress((void**)&A,  g_A);
    cudaGetSymbolAddress((void**)&Bb, g_B);
    cudaGetSymbolAddress((void**)&WP, g_WP);

    static bool attr_set = false;
    if (!attr_set) {
        cudaFuncSetAttribute(kgjbf_k, cudaFuncAttributeMaxDynamicSharedMemorySize, KGJ_SMEM);
        cudaFuncSetAttribute(conv3x3_k<true,false>,
                             cudaFuncAttributeMaxDynamicSharedMemorySize, CONV_SMEM);
        cudaFuncSetAttribute(conv3x3_k<false,true>,
                             cudaFuncAttributeMaxDynamicSharedMemorySize, CONV_SMEM);
        attr_set = true;
    }

    dim3 blk(256);
    dim3 gf(HW/512, 2, Bn);
    dim3 g3(Ww/32, Hh/8, Bn);
    dim3 gj(HW/256, 2, Bn);

    // pack all six 3x3 conv weight tensors (layer order: kg1..kg4, jbf1, jbf2)
    pack_w_k<<<(110592 + 255)/256, blk>>>(kg_w1, kg_w2, kg_w3, kg_w4, jbf_w1, jbf_w2, WP);

    fuse1x1_k<<<gf, blk>>>(image, guidance, tensor_w, tensor_b, a_jbf, A);
    conv3x3_k<true,false><<<g3, blk, CONV_SMEM>>>(A,  WP + 0*18432, kg_b1, a_kg, nullptr, Bb);
    conv3x3_k<true,false><<<g3, blk, CONV_SMEM>>>(Bb, WP + 1*18432, kg_b2, a_kg, nullptr, A);
    conv3x3_k<true,false><<<g3, blk, CONV_SMEM>>>(A,  WP + 2*18432, kg_b3, a_kg, nullptr, Bb);
    conv3x3_k<true,false><<<g3, blk, CONV_SMEM>>>(Bb, WP + 3*18432, kg_b4, a_kg, nullptr, A);
    kgjbf_k<<<gj, blk, KGJ_SMEM>>>(A, kg_w5, kg_b5, image, Bb);
    conv3x3_k<true,false><<<g3, blk, CONV_SMEM>>>(Bb, WP + 4*18432, jbf_b1, a_jbf, nullptr, A);
    conv3x3_k<false,true><<<g3, blk, CONV_SMEM>>>(A,  WP + 5*18432, jbf_b2, nullptr, image, out);
}